// round 1
// baseline (speedup 1.0000x reference)
#include <cuda_runtime.h>

// Problem constants (fixed for this problem instance)
#define Bc   2
#define Sc   2048
#define Dc   1024
#define Hc   16
#define HDc  64
#define Wc   128

// Scratch (allocation-free rule: __device__ globals)
__device__ float g_qkv[Bc * Sc * 3 * Dc];   // [B,S,3D]  ~50 MB
__device__ float g_attn[Bc * Sc * Dc];      // [B,S,D]   ~17 MB

// ---------------------------------------------------------------------------
// GEMM: C[M,N] = A[M,K] @ Wt[N,K]^T + bias[N]
// 64x64 block tile, 256 threads, 4x4 micro tile, K-tile 32.
// Both operands stored transposed in smem (pitch 68) for LDS.128 reads.
// ---------------------------------------------------------------------------
__global__ __launch_bounds__(256) void gemm_bias(
    const float* __restrict__ A, const float* __restrict__ Wt,
    const float* __restrict__ bias, float* __restrict__ C,
    int M, int N, int K)
{
    __shared__ float As[32][68];
    __shared__ float Bs[32][68];

    const int tid = threadIdx.x;
    const int tx = tid & 15;        // 0..15 -> n
    const int ty = tid >> 4;        // 0..15 -> m
    const int m0 = blockIdx.y * 64;
    const int n0 = blockIdx.x * 64;

    const int lr = tid >> 3;        // 0..31
    const int lc = (tid & 7) * 4;   // 0,4,...,28

    float acc[4][4];
#pragma unroll
    for (int i = 0; i < 4; i++)
#pragma unroll
        for (int j = 0; j < 4; j++) acc[i][j] = 0.f;

    for (int k0 = 0; k0 < K; k0 += 32) {
#pragma unroll
        for (int h = 0; h < 2; h++) {
            int r = lr + h * 32;
            float4 a = *(const float4*)&A[(size_t)(m0 + r) * K + k0 + lc];
            As[lc + 0][r] = a.x; As[lc + 1][r] = a.y;
            As[lc + 2][r] = a.z; As[lc + 3][r] = a.w;
            float4 b = *(const float4*)&Wt[(size_t)(n0 + r) * K + k0 + lc];
            Bs[lc + 0][r] = b.x; Bs[lc + 1][r] = b.y;
            Bs[lc + 2][r] = b.z; Bs[lc + 3][r] = b.w;
        }
        __syncthreads();

#pragma unroll 8
        for (int kk = 0; kk < 32; kk++) {
            float4 a4 = *(const float4*)&As[kk][ty * 4];
            float4 b4 = *(const float4*)&Bs[kk][tx * 4];
            float av[4] = {a4.x, a4.y, a4.z, a4.w};
            float bv[4] = {b4.x, b4.y, b4.z, b4.w};
#pragma unroll
            for (int i = 0; i < 4; i++)
#pragma unroll
                for (int j = 0; j < 4; j++)
                    acc[i][j] += av[i] * bv[j];
        }
        __syncthreads();
    }

    const int n = n0 + tx * 4;
    float4 bv4 = *(const float4*)&bias[n];
#pragma unroll
    for (int i = 0; i < 4; i++) {
        float4 o;
        o.x = acc[i][0] + bv4.x;
        o.y = acc[i][1] + bv4.y;
        o.z = acc[i][2] + bv4.z;
        o.w = acc[i][3] + bv4.w;
        *(float4*)&C[(size_t)(m0 + ty * 4 + i) * N + n] = o;
    }
}

// ---------------------------------------------------------------------------
// Windowed attention, flash-style. One block = one (b,h) and 64 queries.
// Exactly 5 key tiles (clipped) of 64 keys. Online softmax in fp32.
// Dynamic smem: Qs[d][q], Ks[d][k], Vs[k][d], Ps[k][q]; pitch 68 floats.
// ---------------------------------------------------------------------------
__global__ __launch_bounds__(256) void attn_kernel(
    const float* __restrict__ qkv, float* __restrict__ out)
{
    extern __shared__ float sm[];
    float (*Qs)[68] = (float(*)[68])(sm);
    float (*Ks)[68] = (float(*)[68])(sm + 64 * 68);
    float (*Vs)[68] = (float(*)[68])(sm + 2 * 64 * 68);
    float (*Ps)[68] = (float(*)[68])(sm + 3 * 64 * 68);

    const int tid = threadIdx.x;
    const int tx = tid & 15;     // -> key cols / out dims
    const int ty = tid >> 4;     // -> query rows
    const int qt = blockIdx.x;
    const int h  = blockIdx.y;
    const int b  = blockIdx.z;
    const int q0 = qt * 64;
    const float scale = 0.125f;  // 1/sqrt(64)

    const size_t base = (size_t)b * Sc * (3 * Dc) + (size_t)h * HDc;

    // Load Q tile transposed, pre-scaled
#pragma unroll
    for (int t = 0; t < 4; t++) {
        int idx = tid + t * 256;
        int r = idx >> 4;          // 0..63 (query row)
        int c = (idx & 15) * 4;    // 0..60 (dim)
        float4 v = *(const float4*)&qkv[base + (size_t)(q0 + r) * (3 * Dc) + c];
        Qs[c + 0][r] = v.x * scale; Qs[c + 1][r] = v.y * scale;
        Qs[c + 2][r] = v.z * scale; Qs[c + 3][r] = v.w * scale;
    }

    float m[4], l[4], o[4][4];
#pragma unroll
    for (int i = 0; i < 4; i++) {
        m[i] = -1e30f; l[i] = 0.f;
#pragma unroll
        for (int j = 0; j < 4; j++) o[i][j] = 0.f;
    }

    const int kt0 = (qt - 2 > 0) ? qt - 2 : 0;
    const int kt1 = (qt + 2 < Sc / 64 - 1) ? qt + 2 : Sc / 64 - 1;

    for (int kt = kt0; kt <= kt1; kt++) {
        const int k0 = kt * 64;
        __syncthreads();  // protect Ks/Vs/Ps from prior iteration consumers
#pragma unroll
        for (int t = 0; t < 4; t++) {
            int idx = tid + t * 256;
            int r = idx >> 4;
            int c = (idx & 15) * 4;
            float4 kv = *(const float4*)&qkv[base + Dc + (size_t)(k0 + r) * (3 * Dc) + c];
            Ks[c + 0][r] = kv.x; Ks[c + 1][r] = kv.y;
            Ks[c + 2][r] = kv.z; Ks[c + 3][r] = kv.w;
            float4 vv = *(const float4*)&qkv[base + 2 * Dc + (size_t)(k0 + r) * (3 * Dc) + c];
            *(float4*)&Vs[r][c] = vv;
        }
        __syncthreads();

        // Scores S = Q K^T (scaled)
        float s[4][4];
#pragma unroll
        for (int i = 0; i < 4; i++)
#pragma unroll
            for (int j = 0; j < 4; j++) s[i][j] = 0.f;

#pragma unroll 8
        for (int d = 0; d < 64; d++) {
            float4 q4 = *(const float4*)&Qs[d][ty * 4];
            float4 k4 = *(const float4*)&Ks[d][tx * 4];
            float qa[4] = {q4.x, q4.y, q4.z, q4.w};
            float ka[4] = {k4.x, k4.y, k4.z, k4.w};
#pragma unroll
            for (int i = 0; i < 4; i++)
#pragma unroll
                for (int j = 0; j < 4; j++)
                    s[i][j] += qa[i] * ka[j];
        }

        // Banded mask |q - k| > W
#pragma unroll
        for (int i = 0; i < 4; i++) {
            int qi = q0 + ty * 4 + i;
#pragma unroll
            for (int j = 0; j < 4; j++) {
                int kj = k0 + tx * 4 + j;
                int d = qi - kj; d = (d < 0) ? -d : d;
                if (d > Wc) s[i][j] = -1e30f;
            }
        }

        // Online softmax (row-groups = 16 consecutive lanes)
#pragma unroll
        for (int i = 0; i < 4; i++) {
            float tm = fmaxf(fmaxf(s[i][0], s[i][1]), fmaxf(s[i][2], s[i][3]));
#pragma unroll
            for (int off = 8; off >= 1; off >>= 1)
                tm = fmaxf(tm, __shfl_xor_sync(0xffffffffu, tm, off));
            float mn = fmaxf(m[i], tm);
            float alpha = __expf(m[i] - mn);
            m[i] = mn;
            float rs = 0.f;
#pragma unroll
            for (int j = 0; j < 4; j++) {
                float p = (s[i][j] > -1e29f) ? __expf(s[i][j] - mn) : 0.f;
                s[i][j] = p;
                rs += p;
            }
#pragma unroll
            for (int off = 8; off >= 1; off >>= 1)
                rs += __shfl_xor_sync(0xffffffffu, rs, off);
            l[i] = l[i] * alpha + rs;
#pragma unroll
            for (int j = 0; j < 4; j++) o[i][j] *= alpha;
        }

        // Stage P transposed: Ps[k][q]
#pragma unroll
        for (int j = 0; j < 4; j++) {
            float4 pv = make_float4(s[0][j], s[1][j], s[2][j], s[3][j]);
            *(float4*)&Ps[tx * 4 + j][ty * 4] = pv;
        }
        __syncthreads();

        // O += P @ V
#pragma unroll 8
        for (int k = 0; k < 64; k++) {
            float4 p4 = *(const float4*)&Ps[k][ty * 4];
            float4 v4 = *(const float4*)&Vs[k][tx * 4];
            float pa[4] = {p4.x, p4.y, p4.z, p4.w};
            float va[4] = {v4.x, v4.y, v4.z, v4.w};
#pragma unroll
            for (int i = 0; i < 4; i++)
#pragma unroll
                for (int j = 0; j < 4; j++)
                    o[i][j] += pa[i] * va[j];
        }
    }

    // Epilogue: normalize, write [B,S,D] layout
#pragma unroll
    for (int i = 0; i < 4; i++) {
        float inv = 1.f / l[i];
        int q = q0 + ty * 4 + i;
        float4 ov = make_float4(o[i][0] * inv, o[i][1] * inv,
                                o[i][2] * inv, o[i][3] * inv);
        *(float4*)&out[((size_t)b * Sc + q) * Dc + (size_t)h * HDc + tx * 4] = ov;
    }
}

// ---------------------------------------------------------------------------
extern "C" void kernel_launch(void* const* d_in, const int* in_sizes, int n_in,
                              void* d_out, int out_size)
{
    (void)in_sizes; (void)n_in; (void)out_size;
    const float* x     = (const float*)d_in[0];
    const float* in_w  = (const float*)d_in[1];  // [3D, D]
    const float* in_b  = (const float*)d_in[2];  // [3D]
    const float* out_w = (const float*)d_in[3];  // [D, D]
    const float* out_b = (const float*)d_in[4];  // [D]
    float* out = (float*)d_out;

    float* qkv;  cudaGetSymbolAddress((void**)&qkv,  g_qkv);
    float* attn; cudaGetSymbolAddress((void**)&attn, g_attn);

    const int M = Bc * Sc;                 // 4096
    const int smem_attn = 4 * 64 * 68 * 4; // 69632 B
    cudaFuncSetAttribute(attn_kernel,
                         cudaFuncAttributeMaxDynamicSharedMemorySize, smem_attn);

    // 1) QKV projection
    gemm_bias<<<dim3(3 * Dc / 64, M / 64), 256>>>(x, in_w, in_b, qkv, M, 3 * Dc, Dc);
    // 2) Windowed attention
    attn_kernel<<<dim3(Sc / 64, Hc, Bc), 256, smem_attn>>>(qkv, attn);
    // 3) Output projection
    gemm_bias<<<dim3(Dc / 64, M / 64), 256>>>(attn, out_w, out_b, out, M, Dc, Dc);
}

// round 2
// speedup vs baseline: 1.6613x; 1.6613x over previous
#include <cuda_runtime.h>
#include <cstdint>

// Problem constants
#define Bc   2
#define Sc   2048
#define Dc   1024
#define Hc   16
#define HDc  64
#define Wc   128

// Scratch (allocation-free rule: __device__ globals)
__device__ float g_qkv[Bc * Sc * 3 * Dc];   // [B,S,3D]
__device__ float g_attn[Bc * Sc * Dc];      // [B,S,D]

__device__ __forceinline__ unsigned f2tf32(float x) {
    unsigned r;
    asm("cvt.rna.tf32.f32 %0, %1;" : "=r"(r) : "f"(x));
    return r;
}

// ---------------------------------------------------------------------------
// TF32 tensor-core GEMM: C[M,N] = A[M,K] @ Wt[N,K]^T + bias[N]
// Block tile 128x128, K-tile 32, 256 threads (8 warps, 2x4 warp grid).
// Smem holds A/B already permuted into m16n8k8 fragment layout + tf32
// converted, so the mainloop is pure LDS.128 + mma.sync.
// ---------------------------------------------------------------------------
__global__ __launch_bounds__(256) void gemm_tf32(
    const float* __restrict__ A, const float* __restrict__ Wt,
    const float* __restrict__ bias, float* __restrict__ C,
    int M, int N, int K)
{
    // A fragments: [kt(4)][mtg(8)] x 128 words ; B fragments: [kt(4)][ntp(8)] x 128
    __shared__ unsigned sA[4096];   // 16 KB
    __shared__ unsigned sB[4096];   // 16 KB

    const int tid    = threadIdx.x;
    const int lane   = tid & 31;
    const int wid    = tid >> 5;
    const int warp_m = wid >> 2;    // 0..1 -> 64-row band
    const int warp_n = wid & 3;     // 0..3 -> 32-col band
    const int m0 = blockIdx.y * 128;
    const int n0 = blockIdx.x * 128;

    float acc[4][4][4];
#pragma unroll
    for (int i = 0; i < 4; i++)
#pragma unroll
        for (int j = 0; j < 4; j++)
#pragma unroll
            for (int c = 0; c < 4; c++) acc[i][j][c] = 0.f;

    // Per-thread gmem float4 slots: f = tid + 256*i, row = f>>3, c4 = (f&7)*4
    float4 ra[4], rb[4];

    // Precompute smem scatter bases (element col i lands at base + 4*i)
    int baseA[4], baseB[4];
#pragma unroll
    for (int i = 0; i < 4; i++) {
        int f  = tid + 256 * i;
        int r  = f >> 3;
        int c4 = (f & 7) * 4;
        int kt = c4 >> 3;
        // A: fragment (kt, mtg) ; lane = (r%8)*4 + col%4 ; slot = (r%16>=8) + 2*(c4%8>=4)
        int mtg  = r >> 4, rr = r & 15;
        int slotA = ((rr >> 3) & 1) + (((c4 & 7) >= 4) ? 2 : 0);
        baseA[i] = (kt * 8 + mtg) * 128 + (rr & 7) * 16 + slotA;
        // B: fragment (kt, ntp) ; lane = 4*(n%8) + col%4 ; off = 2*(nt&1) + (c4%8)/4
        int n = r, nn = n & 7, nt = n >> 3;
        int ntp = nt >> 1, e = nt & 1;
        int slotB = ((c4 & 7) >> 2) & 1;
        baseB[i] = (kt * 8 + ntp) * 128 + nn * 16 + 2 * e + slotB;
    }

    const float* Ap = A + (size_t)m0 * K;
    const float* Bp = Wt + (size_t)n0 * K;

    // Prefetch first K-tile
#pragma unroll
    for (int i = 0; i < 4; i++) {
        int f = tid + 256 * i;
        int r = f >> 3, c4 = (f & 7) * 4;
        ra[i] = *(const float4*)&Ap[(size_t)r * K + c4];
        rb[i] = *(const float4*)&Bp[(size_t)r * K + c4];
    }

    for (int k0 = 0; k0 < K; k0 += 32) {
        __syncthreads();   // previous tile fully consumed
#pragma unroll
        for (int i = 0; i < 4; i++) {
            sA[baseA[i] + 0]  = f2tf32(ra[i].x);
            sA[baseA[i] + 4]  = f2tf32(ra[i].y);
            sA[baseA[i] + 8]  = f2tf32(ra[i].z);
            sA[baseA[i] + 12] = f2tf32(ra[i].w);
            sB[baseB[i] + 0]  = f2tf32(rb[i].x);
            sB[baseB[i] + 4]  = f2tf32(rb[i].y);
            sB[baseB[i] + 8]  = f2tf32(rb[i].z);
            sB[baseB[i] + 12] = f2tf32(rb[i].w);
        }
        __syncthreads();

        if (k0 + 32 < K) {
#pragma unroll
            for (int i = 0; i < 4; i++) {
                int f = tid + 256 * i;
                int r = f >> 3, c4 = (f & 7) * 4;
                ra[i] = *(const float4*)&Ap[(size_t)r * K + k0 + 32 + c4];
                rb[i] = *(const float4*)&Bp[(size_t)r * K + k0 + 32 + c4];
            }
        }

#pragma unroll
        for (int kt = 0; kt < 4; kt++) {
            uint4 af[4], bf[2];
#pragma unroll
            for (int mt = 0; mt < 4; mt++)
                af[mt] = *(const uint4*)&sA[(kt * 8 + warp_m * 4 + mt) * 128 + lane * 4];
#pragma unroll
            for (int p = 0; p < 2; p++)
                bf[p] = *(const uint4*)&sB[(kt * 8 + warp_n * 2 + p) * 128 + lane * 4];

#pragma unroll
            for (int mt = 0; mt < 4; mt++) {
#pragma unroll
                for (int nt = 0; nt < 4; nt++) {
                    const uint4& b4 = bf[nt >> 1];
                    unsigned b0 = (nt & 1) ? b4.z : b4.x;
                    unsigned b1 = (nt & 1) ? b4.w : b4.y;
                    float* c = acc[mt][nt];
                    asm volatile(
                        "mma.sync.aligned.m16n8k8.row.col.f32.tf32.tf32.f32 "
                        "{%0,%1,%2,%3}, {%4,%5,%6,%7}, {%8,%9}, {%0,%1,%2,%3};\n"
                        : "+f"(c[0]), "+f"(c[1]), "+f"(c[2]), "+f"(c[3])
                        : "r"(af[mt].x), "r"(af[mt].y), "r"(af[mt].z), "r"(af[mt].w),
                          "r"(b0), "r"(b1));
                }
            }
        }
    }

    // Epilogue: C fragment layout c0,c1 -> (row, 2c+{0,1}); c2,c3 -> (row+8, ...)
#pragma unroll
    for (int mt = 0; mt < 4; mt++) {
        int row = m0 + warp_m * 64 + mt * 16 + (lane >> 2);
#pragma unroll
        for (int nt = 0; nt < 4; nt++) {
            int col = n0 + warp_n * 32 + nt * 8 + 2 * (lane & 3);
            float2 bv = *(const float2*)&bias[col];
            float2 o0 = make_float2(acc[mt][nt][0] + bv.x, acc[mt][nt][1] + bv.y);
            float2 o1 = make_float2(acc[mt][nt][2] + bv.x, acc[mt][nt][3] + bv.y);
            *(float2*)&C[(size_t)row * N + col]       = o0;
            *(float2*)&C[(size_t)(row + 8) * N + col] = o1;
        }
    }
}

// ---------------------------------------------------------------------------
// Windowed attention, flash-style fp32 (unchanged from R1 baseline).
// ---------------------------------------------------------------------------
__global__ __launch_bounds__(256) void attn_kernel(
    const float* __restrict__ qkv, float* __restrict__ out)
{
    extern __shared__ float sm[];
    float (*Qs)[68] = (float(*)[68])(sm);
    float (*Ks)[68] = (float(*)[68])(sm + 64 * 68);
    float (*Vs)[68] = (float(*)[68])(sm + 2 * 64 * 68);
    float (*Ps)[68] = (float(*)[68])(sm + 3 * 64 * 68);

    const int tid = threadIdx.x;
    const int tx = tid & 15;
    const int ty = tid >> 4;
    const int qt = blockIdx.x;
    const int h  = blockIdx.y;
    const int b  = blockIdx.z;
    const int q0 = qt * 64;
    const float scale = 0.125f;

    const size_t base = (size_t)b * Sc * (3 * Dc) + (size_t)h * HDc;

#pragma unroll
    for (int t = 0; t < 4; t++) {
        int idx = tid + t * 256;
        int r = idx >> 4;
        int c = (idx & 15) * 4;
        float4 v = *(const float4*)&qkv[base + (size_t)(q0 + r) * (3 * Dc) + c];
        Qs[c + 0][r] = v.x * scale; Qs[c + 1][r] = v.y * scale;
        Qs[c + 2][r] = v.z * scale; Qs[c + 3][r] = v.w * scale;
    }

    float m[4], l[4], o[4][4];
#pragma unroll
    for (int i = 0; i < 4; i++) {
        m[i] = -1e30f; l[i] = 0.f;
#pragma unroll
        for (int j = 0; j < 4; j++) o[i][j] = 0.f;
    }

    const int kt0 = (qt - 2 > 0) ? qt - 2 : 0;
    const int kt1 = (qt + 2 < Sc / 64 - 1) ? qt + 2 : Sc / 64 - 1;

    for (int kt = kt0; kt <= kt1; kt++) {
        const int k0 = kt * 64;
        __syncthreads();
#pragma unroll
        for (int t = 0; t < 4; t++) {
            int idx = tid + t * 256;
            int r = idx >> 4;
            int c = (idx & 15) * 4;
            float4 kv = *(const float4*)&qkv[base + Dc + (size_t)(k0 + r) * (3 * Dc) + c];
            Ks[c + 0][r] = kv.x; Ks[c + 1][r] = kv.y;
            Ks[c + 2][r] = kv.z; Ks[c + 3][r] = kv.w;
            float4 vv = *(const float4*)&qkv[base + 2 * Dc + (size_t)(k0 + r) * (3 * Dc) + c];
            *(float4*)&Vs[r][c] = vv;
        }
        __syncthreads();

        float s[4][4];
#pragma unroll
        for (int i = 0; i < 4; i++)
#pragma unroll
            for (int j = 0; j < 4; j++) s[i][j] = 0.f;

#pragma unroll 8
        for (int d = 0; d < 64; d++) {
            float4 q4 = *(const float4*)&Qs[d][ty * 4];
            float4 k4 = *(const float4*)&Ks[d][tx * 4];
            float qa[4] = {q4.x, q4.y, q4.z, q4.w};
            float ka[4] = {k4.x, k4.y, k4.z, k4.w};
#pragma unroll
            for (int i = 0; i < 4; i++)
#pragma unroll
                for (int j = 0; j < 4; j++)
                    s[i][j] += qa[i] * ka[j];
        }

#pragma unroll
        for (int i = 0; i < 4; i++) {
            int qi = q0 + ty * 4 + i;
#pragma unroll
            for (int j = 0; j < 4; j++) {
                int kj = k0 + tx * 4 + j;
                int d = qi - kj; d = (d < 0) ? -d : d;
                if (d > Wc) s[i][j] = -1e30f;
            }
        }

#pragma unroll
        for (int i = 0; i < 4; i++) {
            float tm = fmaxf(fmaxf(s[i][0], s[i][1]), fmaxf(s[i][2], s[i][3]));
#pragma unroll
            for (int off = 8; off >= 1; off >>= 1)
                tm = fmaxf(tm, __shfl_xor_sync(0xffffffffu, tm, off));
            float mn = fmaxf(m[i], tm);
            float alpha = __expf(m[i] - mn);
            m[i] = mn;
            float rs = 0.f;
#pragma unroll
            for (int j = 0; j < 4; j++) {
                float p = (s[i][j] > -1e29f) ? __expf(s[i][j] - mn) : 0.f;
                s[i][j] = p;
                rs += p;
            }
#pragma unroll
            for (int off = 8; off >= 1; off >>= 1)
                rs += __shfl_xor_sync(0xffffffffu, rs, off);
            l[i] = l[i] * alpha + rs;
#pragma unroll
            for (int j = 0; j < 4; j++) o[i][j] *= alpha;
        }

#pragma unroll
        for (int j = 0; j < 4; j++) {
            float4 pv = make_float4(s[0][j], s[1][j], s[2][j], s[3][j]);
            *(float4*)&Ps[tx * 4 + j][ty * 4] = pv;
        }
        __syncthreads();

#pragma unroll 8
        for (int k = 0; k < 64; k++) {
            float4 p4 = *(const float4*)&Ps[k][ty * 4];
            float4 v4 = *(const float4*)&Vs[k][tx * 4];
            float pa[4] = {p4.x, p4.y, p4.z, p4.w};
            float va[4] = {v4.x, v4.y, v4.z, v4.w};
#pragma unroll
            for (int i = 0; i < 4; i++)
#pragma unroll
                for (int j = 0; j < 4; j++)
                    o[i][j] += pa[i] * va[j];
        }
    }

#pragma unroll
    for (int i = 0; i < 4; i++) {
        float inv = 1.f / l[i];
        int q = q0 + ty * 4 + i;
        float4 ov = make_float4(o[i][0] * inv, o[i][1] * inv,
                                o[i][2] * inv, o[i][3] * inv);
        *(float4*)&out[((size_t)b * Sc + q) * Dc + (size_t)h * HDc + tx * 4] = ov;
    }
}

// ---------------------------------------------------------------------------
extern "C" void kernel_launch(void* const* d_in, const int* in_sizes, int n_in,
                              void* d_out, int out_size)
{
    (void)in_sizes; (void)n_in; (void)out_size;
    const float* x     = (const float*)d_in[0];
    const float* in_w  = (const float*)d_in[1];
    const float* in_b  = (const float*)d_in[2];
    const float* out_w = (const float*)d_in[3];
    const float* out_b = (const float*)d_in[4];
    float* out = (float*)d_out;

    float* qkv;  cudaGetSymbolAddress((void**)&qkv,  g_qkv);
    float* attn; cudaGetSymbolAddress((void**)&attn, g_attn);

    const int M = Bc * Sc;                 // 4096
    const int smem_attn = 4 * 64 * 68 * 4; // 69632 B
    cudaFuncSetAttribute(attn_kernel,
                         cudaFuncAttributeMaxDynamicSharedMemorySize, smem_attn);

    // 1) QKV projection (tensor cores, TF32)
    gemm_tf32<<<dim3(3 * Dc / 128, M / 128), 256>>>(x, in_w, in_b, qkv, M, 3 * Dc, Dc);
    // 2) Windowed attention (fp32)
    attn_kernel<<<dim3(Sc / 64, Hc, Bc), 256, smem_attn>>>(qkv, attn);
    // 3) Output projection (tensor cores, TF32)
    gemm_tf32<<<dim3(Dc / 128, M / 128), 256>>>(attn, out_w, out_b, out, M, Dc, Dc);
}

// round 3
// speedup vs baseline: 2.4018x; 1.4458x over previous
#include <cuda_runtime.h>
#include <cstdint>

// Problem constants
#define Bc   2
#define Sc   2048
#define Dc   1024
#define Hc   16
#define HDc  64
#define Wc   128

__device__ float g_qkv[Bc * Sc * 3 * Dc];   // [B,S,3D]
__device__ float g_attn[Bc * Sc * Dc];      // [B,S,D]

__device__ __forceinline__ unsigned f2tf32(float x) {
    unsigned r;
    asm("cvt.rna.tf32.f32 %0, %1;" : "=r"(r) : "f"(x));
    return r;
}

// ---------------------------------------------------------------------------
// TF32 tensor-core GEMM: C[M,N] = A[M,K] @ Wt[N,K]^T + bias[N]
// 128x128 block tile, K-tile 32, 256 threads (8 warps 2x4).
// Smem holds fragment-permuted tf32 data; lane slots XOR-swizzled by kt so
// both STS (write) and LDS.128 (read) are bank-conflict-free.
// Double buffered: one __syncthreads per K-tile.
// ---------------------------------------------------------------------------
__global__ __launch_bounds__(256) void gemm_tf32(
    const float* __restrict__ A, const float* __restrict__ Wt,
    const float* __restrict__ bias, float* __restrict__ C,
    int M, int N, int K)
{
    extern __shared__ unsigned smg[];   // [2][ A:4096 | B:4096 ]  = 64 KB

    const int tid    = threadIdx.x;
    const int lane   = tid & 31;
    const int wid    = tid >> 5;
    const int warp_m = wid >> 2;
    const int warp_n = wid & 3;
    const int m0 = blockIdx.y * 128;
    const int n0 = blockIdx.x * 128;

    float acc[4][4][4];
#pragma unroll
    for (int i = 0; i < 4; i++)
#pragma unroll
        for (int j = 0; j < 4; j++)
#pragma unroll
            for (int c = 0; c < 4; c++) acc[i][j][c] = 0.f;

    // Per-thread load-slot precompute.
    // Warp row pattern {g, g+1, g+8, g+9}: q bit0->r0, bit1->r3, bits2,3->r1,r2, rest->r4+
    int stA[4], stB[4], ktv[4];
    size_t goff[4];
#pragma unroll
    for (int i = 0; i < 4; i++) {
        int f  = tid + 256 * i;
        int q  = f >> 3;
        int c4 = (f & 7) * 4;
        int r  = (q & 1) | (((q >> 1) & 1) << 3) | (((q >> 2) & 3) << 1) | ((q >> 4) << 4);
        int kt = c4 >> 3;
        int sb = ((c4 & 7) >= 4) ? 1 : 0;
        ktv[i] = kt;
        goff[i] = (size_t)r * K + c4;
        // A element (rr, k): lane = (rr&7)*4 + (k&3), slot = (rr>>3) + 2*sb
        int mtg = r >> 4, rr = r & 15;
        stA[i] = (kt * 8 + mtg) * 128 + (rr & 7) * 16 + (rr >> 3) + 2 * sb;
        // B element (n, k): lane = (n&7)*4 + (k&3), slot = 2*((n>>3)&1) + sb
        int ntp = r >> 4, e = (r >> 3) & 1, nn = r & 7;
        stB[i] = (kt * 8 + ntp) * 128 + nn * 16 + 2 * e + sb;
    }

    const float* Ap = A + (size_t)m0 * K;
    const float* Bp = Wt + (size_t)n0 * K;

    float4 ra[4], rb[4];
#pragma unroll
    for (int i = 0; i < 4; i++) {
        ra[i] = *(const float4*)&Ap[goff[i]];
        rb[i] = *(const float4*)&Bp[goff[i]];
    }

    const int nT = K / 32;

    // Store tile 0 into buffer 0
    {
        unsigned* sA = smg;
        unsigned* sB = smg + 4096;
#pragma unroll
        for (int i = 0; i < 4; i++) {
            int x = ktv[i] << 2;
            float av[4] = {ra[i].x, ra[i].y, ra[i].z, ra[i].w};
            float bv[4] = {rb[i].x, rb[i].y, rb[i].z, rb[i].w};
#pragma unroll
            for (int e = 0; e < 4; e++) {
                sA[stA[i] + ((e << 2) ^ x)] = f2tf32(av[e]);
                sB[stB[i] + ((e << 2) ^ x)] = f2tf32(bv[e]);
            }
        }
    }
    __syncthreads();

    for (int t = 0; t < nT; t++) {
        const unsigned* sA = smg + (t & 1) * 8192;
        const unsigned* sB = sA + 4096;

        if (t + 1 < nT) {
            int k0 = (t + 1) * 32;
#pragma unroll
            for (int i = 0; i < 4; i++) {
                ra[i] = *(const float4*)&Ap[goff[i] + k0];
                rb[i] = *(const float4*)&Bp[goff[i] + k0];
            }
        }

#pragma unroll
        for (int kt = 0; kt < 4; kt++) {
            const int lx = (lane ^ kt) << 2;
            uint4 af[4], bf[2];
#pragma unroll
            for (int mt = 0; mt < 4; mt++)
                af[mt] = *(const uint4*)&sA[(kt * 8 + warp_m * 4 + mt) * 128 + lx];
#pragma unroll
            for (int p = 0; p < 2; p++)
                bf[p] = *(const uint4*)&sB[(kt * 8 + warp_n * 2 + p) * 128 + lx];

#pragma unroll
            for (int mt = 0; mt < 4; mt++) {
#pragma unroll
                for (int nt = 0; nt < 4; nt++) {
                    const uint4& b4 = bf[nt >> 1];
                    unsigned b0 = (nt & 1) ? b4.z : b4.x;
                    unsigned b1 = (nt & 1) ? b4.w : b4.y;
                    float* c = acc[mt][nt];
                    asm volatile(
                        "mma.sync.aligned.m16n8k8.row.col.f32.tf32.tf32.f32 "
                        "{%0,%1,%2,%3}, {%4,%5,%6,%7}, {%8,%9}, {%0,%1,%2,%3};\n"
                        : "+f"(c[0]), "+f"(c[1]), "+f"(c[2]), "+f"(c[3])
                        : "r"(af[mt].x), "r"(af[mt].y), "r"(af[mt].z), "r"(af[mt].w),
                          "r"(b0), "r"(b1));
                }
            }
        }

        if (t + 1 < nT) {
            unsigned* dA = smg + ((t + 1) & 1) * 8192;
            unsigned* dB = dA + 4096;
#pragma unroll
            for (int i = 0; i < 4; i++) {
                int x = ktv[i] << 2;
                float av[4] = {ra[i].x, ra[i].y, ra[i].z, ra[i].w};
                float bv[4] = {rb[i].x, rb[i].y, rb[i].z, rb[i].w};
#pragma unroll
                for (int e = 0; e < 4; e++) {
                    dA[stA[i] + ((e << 2) ^ x)] = f2tf32(av[e]);
                    dB[stB[i] + ((e << 2) ^ x)] = f2tf32(bv[e]);
                }
            }
            __syncthreads();
        }
    }

    // Epilogue
#pragma unroll
    for (int mt = 0; mt < 4; mt++) {
        int row = m0 + warp_m * 64 + mt * 16 + (lane >> 2);
#pragma unroll
        for (int nt = 0; nt < 4; nt++) {
            int col = n0 + warp_n * 32 + nt * 8 + 2 * (lane & 3);
            float2 bv = *(const float2*)&bias[col];
            float2 o0 = make_float2(acc[mt][nt][0] + bv.x, acc[mt][nt][1] + bv.y);
            float2 o1 = make_float2(acc[mt][nt][2] + bv.x, acc[mt][nt][3] + bv.y);
            *(float2*)&C[(size_t)row * N + col]       = o0;
            *(float2*)&C[(size_t)(row + 8) * N + col] = o1;
        }
    }
}

// ---------------------------------------------------------------------------
// Windowed attention, flash-style fp32 (unchanged).
// ---------------------------------------------------------------------------
__global__ __launch_bounds__(256) void attn_kernel(
    const float* __restrict__ qkv, float* __restrict__ out)
{
    extern __shared__ float sm[];
    float (*Qs)[68] = (float(*)[68])(sm);
    float (*Ks)[68] = (float(*)[68])(sm + 64 * 68);
    float (*Vs)[68] = (float(*)[68])(sm + 2 * 64 * 68);
    float (*Ps)[68] = (float(*)[68])(sm + 3 * 64 * 68);

    const int tid = threadIdx.x;
    const int tx = tid & 15;
    const int ty = tid >> 4;
    const int qt = blockIdx.x;
    const int h  = blockIdx.y;
    const int b  = blockIdx.z;
    const int q0 = qt * 64;
    const float scale = 0.125f;

    const size_t base = (size_t)b * Sc * (3 * Dc) + (size_t)h * HDc;

#pragma unroll
    for (int t = 0; t < 4; t++) {
        int idx = tid + t * 256;
        int r = idx >> 4;
        int c = (idx & 15) * 4;
        float4 v = *(const float4*)&qkv[base + (size_t)(q0 + r) * (3 * Dc) + c];
        Qs[c + 0][r] = v.x * scale; Qs[c + 1][r] = v.y * scale;
        Qs[c + 2][r] = v.z * scale; Qs[c + 3][r] = v.w * scale;
    }

    float m[4], l[4], o[4][4];
#pragma unroll
    for (int i = 0; i < 4; i++) {
        m[i] = -1e30f; l[i] = 0.f;
#pragma unroll
        for (int j = 0; j < 4; j++) o[i][j] = 0.f;
    }

    const int kt0 = (qt - 2 > 0) ? qt - 2 : 0;
    const int kt1 = (qt + 2 < Sc / 64 - 1) ? qt + 2 : Sc / 64 - 1;

    for (int kt = kt0; kt <= kt1; kt++) {
        const int k0 = kt * 64;
        __syncthreads();
#pragma unroll
        for (int t = 0; t < 4; t++) {
            int idx = tid + t * 256;
            int r = idx >> 4;
            int c = (idx & 15) * 4;
            float4 kv = *(const float4*)&qkv[base + Dc + (size_t)(k0 + r) * (3 * Dc) + c];
            Ks[c + 0][r] = kv.x; Ks[c + 1][r] = kv.y;
            Ks[c + 2][r] = kv.z; Ks[c + 3][r] = kv.w;
            float4 vv = *(const float4*)&qkv[base + 2 * Dc + (size_t)(k0 + r) * (3 * Dc) + c];
            *(float4*)&Vs[r][c] = vv;
        }
        __syncthreads();

        float s[4][4];
#pragma unroll
        for (int i = 0; i < 4; i++)
#pragma unroll
            for (int j = 0; j < 4; j++) s[i][j] = 0.f;

#pragma unroll 8
        for (int d = 0; d < 64; d++) {
            float4 q4 = *(const float4*)&Qs[d][ty * 4];
            float4 k4 = *(const float4*)&Ks[d][tx * 4];
            float qa[4] = {q4.x, q4.y, q4.z, q4.w};
            float ka[4] = {k4.x, k4.y, k4.z, k4.w};
#pragma unroll
            for (int i = 0; i < 4; i++)
#pragma unroll
                for (int j = 0; j < 4; j++)
                    s[i][j] += qa[i] * ka[j];
        }

#pragma unroll
        for (int i = 0; i < 4; i++) {
            int qi = q0 + ty * 4 + i;
#pragma unroll
            for (int j = 0; j < 4; j++) {
                int kj = k0 + tx * 4 + j;
                int d = qi - kj; d = (d < 0) ? -d : d;
                if (d > Wc) s[i][j] = -1e30f;
            }
        }

#pragma unroll
        for (int i = 0; i < 4; i++) {
            float tm = fmaxf(fmaxf(s[i][0], s[i][1]), fmaxf(s[i][2], s[i][3]));
#pragma unroll
            for (int off = 8; off >= 1; off >>= 1)
                tm = fmaxf(tm, __shfl_xor_sync(0xffffffffu, tm, off));
            float mn = fmaxf(m[i], tm);
            float alpha = __expf(m[i] - mn);
            m[i] = mn;
            float rs = 0.f;
#pragma unroll
            for (int j = 0; j < 4; j++) {
                float p = (s[i][j] > -1e29f) ? __expf(s[i][j] - mn) : 0.f;
                s[i][j] = p;
                rs += p;
            }
#pragma unroll
            for (int off = 8; off >= 1; off >>= 1)
                rs += __shfl_xor_sync(0xffffffffu, rs, off);
            l[i] = l[i] * alpha + rs;
#pragma unroll
            for (int j = 0; j < 4; j++) o[i][j] *= alpha;
        }

#pragma unroll
        for (int j = 0; j < 4; j++) {
            float4 pv = make_float4(s[0][j], s[1][j], s[2][j], s[3][j]);
            *(float4*)&Ps[tx * 4 + j][ty * 4] = pv;
        }
        __syncthreads();

#pragma unroll 8
        for (int k = 0; k < 64; k++) {
            float4 p4 = *(const float4*)&Ps[k][ty * 4];
            float4 v4 = *(const float4*)&Vs[k][tx * 4];
            float pa[4] = {p4.x, p4.y, p4.z, p4.w};
            float va[4] = {v4.x, v4.y, v4.z, v4.w};
#pragma unroll
            for (int i = 0; i < 4; i++)
#pragma unroll
                for (int j = 0; j < 4; j++)
                    o[i][j] += pa[i] * va[j];
        }
    }

#pragma unroll
    for (int i = 0; i < 4; i++) {
        float inv = 1.f / l[i];
        int q = q0 + ty * 4 + i;
        float4 ov = make_float4(o[i][0] * inv, o[i][1] * inv,
                                o[i][2] * inv, o[i][3] * inv);
        *(float4*)&out[((size_t)b * Sc + q) * Dc + (size_t)h * HDc + tx * 4] = ov;
    }
}

// ---------------------------------------------------------------------------
extern "C" void kernel_launch(void* const* d_in, const int* in_sizes, int n_in,
                              void* d_out, int out_size)
{
    (void)in_sizes; (void)n_in; (void)out_size;
    const float* x     = (const float*)d_in[0];
    const float* in_w  = (const float*)d_in[1];
    const float* in_b  = (const float*)d_in[2];
    const float* out_w = (const float*)d_in[3];
    const float* out_b = (const float*)d_in[4];
    float* out = (float*)d_out;

    float* qkv;  cudaGetSymbolAddress((void**)&qkv,  g_qkv);
    float* attn; cudaGetSymbolAddress((void**)&attn, g_attn);

    const int M = Bc * Sc;                  // 4096
    const int smem_gemm = 16384 * 4;        // 64 KB (double-buffered)
    const int smem_attn = 4 * 64 * 68 * 4;  // 69632 B
    cudaFuncSetAttribute(gemm_tf32,
                         cudaFuncAttributeMaxDynamicSharedMemorySize, smem_gemm);
    cudaFuncSetAttribute(attn_kernel,
                         cudaFuncAttributeMaxDynamicSharedMemorySize, smem_attn);

    gemm_tf32<<<dim3(3 * Dc / 128, M / 128), 256, smem_gemm>>>(x, in_w, in_b, qkv, M, 3 * Dc, Dc);
    attn_kernel<<<dim3(Sc / 64, Hc, Bc), 256, smem_attn>>>(qkv, attn);
    gemm_tf32<<<dim3(Dc / 128, M / 128), 256, smem_gemm>>>(attn, out_w, out_b, out, M, Dc, Dc);
}

// round 4
// speedup vs baseline: 2.9400x; 1.2241x over previous
#include <cuda_runtime.h>
#include <cstdint>

// Problem constants
#define Bc   2
#define Sc   2048
#define Dc   1024
#define Hc   16
#define HDc  64
#define Wc   128

// Scratch (allocation-free rule: __device__ globals)
__device__ float    g_qkv[Bc * Sc * 3 * Dc];       // [B,S,3D]
__device__ float    g_attn[Bc * Sc * Dc];          // [B,S,D]
__device__ unsigned g_xperm[Bc * Sc * Dc];         // x in A-fragment layout (tf32)
__device__ unsigned g_attnperm[Bc * Sc * Dc];      // attn out in A-fragment layout
__device__ unsigned g_wqkvperm[3 * Dc * Dc];       // in_proj_w in B-fragment layout
__device__ unsigned g_woutperm[Dc * Dc];           // out_proj_w in B-fragment layout

__device__ __forceinline__ unsigned f2tf32(float x) {
    unsigned r;
    asm("cvt.rna.tf32.f32 %0, %1;" : "=r"(r) : "f"(x));
    return r;
}

// ---------------------------------------------------------------------------
// Permute X[M][K] (row-major fp32) into A-operand mma fragment layout (tf32):
// P[mblk][kblk][kt][mtg][lane][slot], slot = {(+0,+0),(+8r,+0),(+0,+4k),(+8r,+4k)}
// One thread per 16B output (coalesced STG.128, strided 4B loads).
// ---------------------------------------------------------------------------
__global__ __launch_bounds__(256) void permA(
    const float* __restrict__ X, unsigned* __restrict__ P, int M, int K)
{
    int idx = blockIdx.x * blockDim.x + threadIdx.x;
    int total = (M * K) >> 2;
    if (idx >= total) return;
    int nKB  = K >> 5;
    int lane = idx & 31;
    int mtg  = (idx >> 5) & 7;
    int kt   = (idx >> 8) & 3;
    int rest = idx >> 10;
    int kblk = rest % nKB;
    int mblk = rest / nKB;
    int r0 = mblk * 128 + mtg * 16 + (lane >> 2);
    int c0 = kblk * 32 + kt * 8 + (lane & 3);
    const float* x = X + (size_t)r0 * K + c0;
    uint4 v;
    v.x = f2tf32(x[0]);
    v.y = f2tf32(x[(size_t)8 * K]);
    v.z = f2tf32(x[4]);
    v.w = f2tf32(x[(size_t)8 * K + 4]);
    ((uint4*)P)[idx] = v;
}

// ---------------------------------------------------------------------------
// Permute W[N][K] (row-major fp32) into B-operand fragment layout (tf32):
// P[nblk][kblk][kt][ntp][lane][slot], slot = 2*e + khalf  (e = +8 n-rows)
// ---------------------------------------------------------------------------
__global__ __launch_bounds__(256) void permB(
    const float* __restrict__ X, unsigned* __restrict__ P, int N, int K)
{
    int idx = blockIdx.x * blockDim.x + threadIdx.x;
    int total = (N * K) >> 2;
    if (idx >= total) return;
    int nKB  = K >> 5;
    int lane = idx & 31;
    int ntp  = (idx >> 5) & 7;
    int kt   = (idx >> 8) & 3;
    int rest = idx >> 10;
    int kblk = rest % nKB;
    int nblk = rest / nKB;
    int n0 = nblk * 128 + ntp * 16 + (lane >> 2);
    int c0 = kblk * 32 + kt * 8 + (lane & 3);
    const float* x = X + (size_t)n0 * K + c0;
    uint4 v;
    v.x = f2tf32(x[0]);
    v.y = f2tf32(x[4]);
    v.z = f2tf32(x[(size_t)8 * K]);
    v.w = f2tf32(x[(size_t)8 * K + 4]);
    ((uint4*)P)[idx] = v;
}

// ---------------------------------------------------------------------------
// TF32 tensor-core GEMM on pre-permuted operands.
// C[M,N] = A @ W^T + bias. 128x128 tile, K-tile 32, 256 threads (2x4 warps).
// Each K-tile is a contiguous 16KB(A)+16KB(B) block: cp.async 3-stage
// pipeline, conflict-free LDS.128, 64 mma per warp per K-tile.
// ---------------------------------------------------------------------------
#define GSTAGES 3
__global__ __launch_bounds__(256, 2) void gemm_tf32p(
    const unsigned* __restrict__ Ap, const unsigned* __restrict__ Bp,
    const float* __restrict__ bias, float* __restrict__ C,
    int M, int N, int K)
{
    extern __shared__ unsigned smg[];   // GSTAGES * 8192 words (A:4096 | B:4096)

    const int tid    = threadIdx.x;
    const int lane   = tid & 31;
    const int wid    = tid >> 5;
    const int warp_m = wid >> 2;
    const int warp_n = wid & 3;
    const int nKB    = K >> 5;

    const unsigned* Atile = Ap + (size_t)blockIdx.y * nKB * 4096;
    const unsigned* Btile = Bp + (size_t)blockIdx.x * nKB * 4096;
    const uint32_t sbase = (uint32_t)__cvta_generic_to_shared(smg);

    float acc[4][4][4];
#pragma unroll
    for (int i = 0; i < 4; i++)
#pragma unroll
        for (int j = 0; j < 4; j++)
#pragma unroll
            for (int c = 0; c < 4; c++) acc[i][j][c] = 0.f;

#define ISSUE_TILE(t)                                                          \
    {                                                                          \
        uint32_t st = sbase + ((t) % GSTAGES) * 32768u;                        \
        const unsigned* asrc = Atile + (size_t)(t) * 4096;                     \
        const unsigned* bsrc = Btile + (size_t)(t) * 4096;                     \
        _Pragma("unroll")                                                      \
        for (int j = 0; j < 4; j++) {                                          \
            int c = tid + 256 * j;                                             \
            asm volatile("cp.async.cg.shared.global [%0],[%1],16;\n"           \
                         :: "r"(st + c * 16u), "l"(asrc + c * 4));             \
            asm volatile("cp.async.cg.shared.global [%0],[%1],16;\n"           \
                         :: "r"(st + 16384u + c * 16u), "l"(bsrc + c * 4));    \
        }                                                                      \
        asm volatile("cp.async.commit_group;\n");                              \
    }

    ISSUE_TILE(0);
    ISSUE_TILE(1);

    for (int t = 0; t < nKB; t++) {
        asm volatile("cp.async.wait_group 1;\n");
        __syncthreads();

        if (t + 2 < nKB) {
            ISSUE_TILE(t + 2);
        } else {
            asm volatile("cp.async.commit_group;\n");
        }

        const unsigned* sA = smg + (t % GSTAGES) * 8192;
        const unsigned* sB = sA + 4096;

#pragma unroll
        for (int kt = 0; kt < 4; kt++) {
            const int lx = lane << 2;
            uint4 af[4], bf[2];
#pragma unroll
            for (int mt = 0; mt < 4; mt++)
                af[mt] = *(const uint4*)&sA[(kt * 8 + warp_m * 4 + mt) * 128 + lx];
#pragma unroll
            for (int p = 0; p < 2; p++)
                bf[p] = *(const uint4*)&sB[(kt * 8 + warp_n * 2 + p) * 128 + lx];

#pragma unroll
            for (int mt = 0; mt < 4; mt++) {
#pragma unroll
                for (int nt = 0; nt < 4; nt++) {
                    const uint4& b4 = bf[nt >> 1];
                    unsigned b0 = (nt & 1) ? b4.z : b4.x;
                    unsigned b1 = (nt & 1) ? b4.w : b4.y;
                    float* c = acc[mt][nt];
                    asm volatile(
                        "mma.sync.aligned.m16n8k8.row.col.f32.tf32.tf32.f32 "
                        "{%0,%1,%2,%3}, {%4,%5,%6,%7}, {%8,%9}, {%0,%1,%2,%3};\n"
                        : "+f"(c[0]), "+f"(c[1]), "+f"(c[2]), "+f"(c[3])
                        : "r"(af[mt].x), "r"(af[mt].y), "r"(af[mt].z), "r"(af[mt].w),
                          "r"(b0), "r"(b1));
                }
            }
        }
    }

    const int m0 = blockIdx.y * 128;
    const int n0 = blockIdx.x * 128;
#pragma unroll
    for (int mt = 0; mt < 4; mt++) {
        int row = m0 + warp_m * 64 + mt * 16 + (lane >> 2);
#pragma unroll
        for (int nt = 0; nt < 4; nt++) {
            int col = n0 + warp_n * 32 + nt * 8 + 2 * (lane & 3);
            float2 bv = *(const float2*)&bias[col];
            float2 o0 = make_float2(acc[mt][nt][0] + bv.x, acc[mt][nt][1] + bv.y);
            float2 o1 = make_float2(acc[mt][nt][2] + bv.x, acc[mt][nt][3] + bv.y);
            *(float2*)&C[(size_t)row * N + col]       = o0;
            *(float2*)&C[(size_t)(row + 8) * N + col] = o1;
        }
    }
}

// ---------------------------------------------------------------------------
// Windowed attention, flash-style fp32 (unchanged).
// ---------------------------------------------------------------------------
__global__ __launch_bounds__(256) void attn_kernel(
    const float* __restrict__ qkv, float* __restrict__ out)
{
    extern __shared__ float sm[];
    float (*Qs)[68] = (float(*)[68])(sm);
    float (*Ks)[68] = (float(*)[68])(sm + 64 * 68);
    float (*Vs)[68] = (float(*)[68])(sm + 2 * 64 * 68);
    float (*Ps)[68] = (float(*)[68])(sm + 3 * 64 * 68);

    const int tid = threadIdx.x;
    const int tx = tid & 15;
    const int ty = tid >> 4;
    const int qt = blockIdx.x;
    const int h  = blockIdx.y;
    const int b  = blockIdx.z;
    const int q0 = qt * 64;
    const float scale = 0.125f;

    const size_t base = (size_t)b * Sc * (3 * Dc) + (size_t)h * HDc;

#pragma unroll
    for (int t = 0; t < 4; t++) {
        int idx = tid + t * 256;
        int r = idx >> 4;
        int c = (idx & 15) * 4;
        float4 v = *(const float4*)&qkv[base + (size_t)(q0 + r) * (3 * Dc) + c];
        Qs[c + 0][r] = v.x * scale; Qs[c + 1][r] = v.y * scale;
        Qs[c + 2][r] = v.z * scale; Qs[c + 3][r] = v.w * scale;
    }

    float m[4], l[4], o[4][4];
#pragma unroll
    for (int i = 0; i < 4; i++) {
        m[i] = -1e30f; l[i] = 0.f;
#pragma unroll
        for (int j = 0; j < 4; j++) o[i][j] = 0.f;
    }

    const int kt0 = (qt - 2 > 0) ? qt - 2 : 0;
    const int kt1 = (qt + 2 < Sc / 64 - 1) ? qt + 2 : Sc / 64 - 1;

    for (int kt = kt0; kt <= kt1; kt++) {
        const int k0 = kt * 64;
        __syncthreads();
#pragma unroll
        for (int t = 0; t < 4; t++) {
            int idx = tid + t * 256;
            int r = idx >> 4;
            int c = (idx & 15) * 4;
            float4 kv = *(const float4*)&qkv[base + Dc + (size_t)(k0 + r) * (3 * Dc) + c];
            Ks[c + 0][r] = kv.x; Ks[c + 1][r] = kv.y;
            Ks[c + 2][r] = kv.z; Ks[c + 3][r] = kv.w;
            float4 vv = *(const float4*)&qkv[base + 2 * Dc + (size_t)(k0 + r) * (3 * Dc) + c];
            *(float4*)&Vs[r][c] = vv;
        }
        __syncthreads();

        float s[4][4];
#pragma unroll
        for (int i = 0; i < 4; i++)
#pragma unroll
            for (int j = 0; j < 4; j++) s[i][j] = 0.f;

#pragma unroll 8
        for (int d = 0; d < 64; d++) {
            float4 q4 = *(const float4*)&Qs[d][ty * 4];
            float4 k4 = *(const float4*)&Ks[d][tx * 4];
            float qa[4] = {q4.x, q4.y, q4.z, q4.w};
            float ka[4] = {k4.x, k4.y, k4.z, k4.w};
#pragma unroll
            for (int i = 0; i < 4; i++)
#pragma unroll
                for (int j = 0; j < 4; j++)
                    s[i][j] += qa[i] * ka[j];
        }

#pragma unroll
        for (int i = 0; i < 4; i++) {
            int qi = q0 + ty * 4 + i;
#pragma unroll
            for (int j = 0; j < 4; j++) {
                int kj = k0 + tx * 4 + j;
                int d = qi - kj; d = (d < 0) ? -d : d;
                if (d > Wc) s[i][j] = -1e30f;
            }
        }

#pragma unroll
        for (int i = 0; i < 4; i++) {
            float tm = fmaxf(fmaxf(s[i][0], s[i][1]), fmaxf(s[i][2], s[i][3]));
#pragma unroll
            for (int off = 8; off >= 1; off >>= 1)
                tm = fmaxf(tm, __shfl_xor_sync(0xffffffffu, tm, off));
            float mn = fmaxf(m[i], tm);
            float alpha = __expf(m[i] - mn);
            m[i] = mn;
            float rs = 0.f;
#pragma unroll
            for (int j = 0; j < 4; j++) {
                float p = (s[i][j] > -1e29f) ? __expf(s[i][j] - mn) : 0.f;
                s[i][j] = p;
                rs += p;
            }
#pragma unroll
            for (int off = 8; off >= 1; off >>= 1)
                rs += __shfl_xor_sync(0xffffffffu, rs, off);
            l[i] = l[i] * alpha + rs;
#pragma unroll
            for (int j = 0; j < 4; j++) o[i][j] *= alpha;
        }

#pragma unroll
        for (int j = 0; j < 4; j++) {
            float4 pv = make_float4(s[0][j], s[1][j], s[2][j], s[3][j]);
            *(float4*)&Ps[tx * 4 + j][ty * 4] = pv;
        }
        __syncthreads();

#pragma unroll 8
        for (int k = 0; k < 64; k++) {
            float4 p4 = *(const float4*)&Ps[k][ty * 4];
            float4 v4 = *(const float4*)&Vs[k][tx * 4];
            float pa[4] = {p4.x, p4.y, p4.z, p4.w};
            float va[4] = {v4.x, v4.y, v4.z, v4.w};
#pragma unroll
            for (int i = 0; i < 4; i++)
#pragma unroll
                for (int j = 0; j < 4; j++)
                    o[i][j] += pa[i] * va[j];
        }
    }

#pragma unroll
    for (int i = 0; i < 4; i++) {
        float inv = 1.f / l[i];
        int q = q0 + ty * 4 + i;
        float4 ov = make_float4(o[i][0] * inv, o[i][1] * inv,
                                o[i][2] * inv, o[i][3] * inv);
        *(float4*)&out[((size_t)b * Sc + q) * Dc + (size_t)h * HDc + tx * 4] = ov;
    }
}

// ---------------------------------------------------------------------------
extern "C" void kernel_launch(void* const* d_in, const int* in_sizes, int n_in,
                              void* d_out, int out_size)
{
    (void)in_sizes; (void)n_in; (void)out_size;
    const float* x     = (const float*)d_in[0];
    const float* in_w  = (const float*)d_in[1];
    const float* in_b  = (const float*)d_in[2];
    const float* out_w = (const float*)d_in[3];
    const float* out_b = (const float*)d_in[4];
    float* out = (float*)d_out;

    float *qkv, *attn;
    unsigned *xp, *ap, *wqp, *wop;
    cudaGetSymbolAddress((void**)&qkv,  g_qkv);
    cudaGetSymbolAddress((void**)&attn, g_attn);
    cudaGetSymbolAddress((void**)&xp,   g_xperm);
    cudaGetSymbolAddress((void**)&ap,   g_attnperm);
    cudaGetSymbolAddress((void**)&wqp,  g_wqkvperm);
    cudaGetSymbolAddress((void**)&wop,  g_woutperm);

    const int M = Bc * Sc;                      // 4096
    const int smem_gemm = GSTAGES * 32768;      // 96 KB
    const int smem_attn = 4 * 64 * 68 * 4;      // 69632 B
    cudaFuncSetAttribute(gemm_tf32p,
                         cudaFuncAttributeMaxDynamicSharedMemorySize, smem_gemm);
    cudaFuncSetAttribute(attn_kernel,
                         cudaFuncAttributeMaxDynamicSharedMemorySize, smem_attn);

    // Operand permutes (x and weights)
    permA<<<(M * Dc / 4 + 255) / 256, 256>>>(x, xp, M, Dc);
    permB<<<(3 * Dc * Dc / 4 + 255) / 256, 256>>>(in_w, wqp, 3 * Dc, Dc);
    permB<<<(Dc * Dc / 4 + 255) / 256, 256>>>(out_w, wop, Dc, Dc);

    // 1) QKV projection
    gemm_tf32p<<<dim3(3 * Dc / 128, M / 128), 256, smem_gemm>>>(
        xp, wqp, in_b, qkv, M, 3 * Dc, Dc);
    // 2) Windowed attention
    attn_kernel<<<dim3(Sc / 64, Hc, Bc), 256, smem_attn>>>(qkv, attn);
    // 3) Permute attention output, then output projection
    permA<<<(M * Dc / 4 + 255) / 256, 256>>>(attn, ap, M, Dc);
    gemm_tf32p<<<dim3(Dc / 128, M / 128), 256, smem_gemm>>>(
        ap, wop, out_b, out, M, Dc, Dc);
}

// round 7
// speedup vs baseline: 3.7931x; 1.2902x over previous
#include <cuda_runtime.h>
#include <cstdint>

// Problem constants
#define Bc   2
#define Sc   2048
#define Dc   1024
#define Hc   16
#define HDc  64
#define Wc   128

// Scratch (allocation-free rule: __device__ globals)
__device__ float    g_qkv[Bc * Sc * 3 * Dc];    // [B,S,3D]
__device__ unsigned g_xperm[Bc * Sc * Dc];      // x in A-fragment layout (tf32)
__device__ unsigned g_attnperm[Bc * Sc * Dc];   // attn out in A-fragment layout
__device__ unsigned g_wqkvperm[3 * Dc * Dc];    // in_proj_w in B-fragment layout
__device__ unsigned g_woutperm[Dc * Dc];        // out_proj_w in B-fragment layout
// Attention fragment buffers (per (b,h,tile64): 4096 words)
__device__ unsigned g_qfh[Bc * Sc * Dc];        // Q A-frag hi (scaled)
__device__ unsigned g_qfl[Bc * Sc * Dc];        // Q A-frag lo
__device__ unsigned g_kfh[Bc * Sc * Dc];        // K B-frag hi
__device__ unsigned g_kfl[Bc * Sc * Dc];        // K B-frag lo
__device__ unsigned g_vf [Bc * Sc * Dc];        // V^T B-frag (n=dim,k=key)

__device__ __forceinline__ unsigned f2tf32(float x) {
    unsigned r;
    asm("cvt.rna.tf32.f32 %0, %1;" : "=r"(r) : "f"(x));
    return r;
}

__device__ __forceinline__ void mma8(float* c, unsigned a0, unsigned a1,
                                     unsigned a2, unsigned a3,
                                     unsigned b0, unsigned b1) {
    asm volatile(
        "mma.sync.aligned.m16n8k8.row.col.f32.tf32.tf32.f32 "
        "{%0,%1,%2,%3}, {%4,%5,%6,%7}, {%8,%9}, {%0,%1,%2,%3};\n"
        : "+f"(c[0]), "+f"(c[1]), "+f"(c[2]), "+f"(c[3])
        : "r"(a0), "r"(a1), "r"(a2), "r"(a3), "r"(b0), "r"(b1));
}

// ---------------------------------------------------------------------------
// permA / permB: projection-GEMM operand packers (unchanged from R4, proven)
// ---------------------------------------------------------------------------
__global__ __launch_bounds__(256) void permA(
    const float* __restrict__ X, unsigned* __restrict__ P, int M, int K)
{
    int idx = blockIdx.x * blockDim.x + threadIdx.x;
    int total = (M * K) >> 2;
    if (idx >= total) return;
    int nKB  = K >> 5;
    int lane = idx & 31;
    int mtg  = (idx >> 5) & 7;
    int kt   = (idx >> 8) & 3;
    int rest = idx >> 10;
    int kblk = rest % nKB;
    int mblk = rest / nKB;
    int r0 = mblk * 128 + mtg * 16 + (lane >> 2);
    int c0 = kblk * 32 + kt * 8 + (lane & 3);
    const float* x = X + (size_t)r0 * K + c0;
    uint4 v;
    v.x = f2tf32(x[0]);
    v.y = f2tf32(x[(size_t)8 * K]);
    v.z = f2tf32(x[4]);
    v.w = f2tf32(x[(size_t)8 * K + 4]);
    ((uint4*)P)[idx] = v;
}

__global__ __launch_bounds__(256) void permB(
    const float* __restrict__ X, unsigned* __restrict__ P, int N, int K)
{
    int idx = blockIdx.x * blockDim.x + threadIdx.x;
    int total = (N * K) >> 2;
    if (idx >= total) return;
    int nKB  = K >> 5;
    int lane = idx & 31;
    int ntp  = (idx >> 5) & 7;
    int kt   = (idx >> 8) & 3;
    int rest = idx >> 10;
    int kblk = rest % nKB;
    int nblk = rest / nKB;
    int n0 = nblk * 128 + ntp * 16 + (lane >> 2);
    int c0 = kblk * 32 + kt * 8 + (lane & 3);
    const float* x = X + (size_t)n0 * K + c0;
    uint4 v;
    v.x = f2tf32(x[0]);
    v.y = f2tf32(x[4]);
    v.z = f2tf32(x[(size_t)8 * K]);
    v.w = f2tf32(x[(size_t)8 * K + 4]);
    ((uint4*)P)[idx] = v;
}

// ---------------------------------------------------------------------------
// Projection GEMM on pre-permuted operands (unchanged from R4, proven).
// ---------------------------------------------------------------------------
#define GSTAGES 3
__global__ __launch_bounds__(256, 2) void gemm_tf32p(
    const unsigned* __restrict__ Ap, const unsigned* __restrict__ Bp,
    const float* __restrict__ bias, float* __restrict__ C,
    int M, int N, int K)
{
    extern __shared__ unsigned smg[];

    const int tid    = threadIdx.x;
    const int lane   = tid & 31;
    const int wid    = tid >> 5;
    const int warp_m = wid >> 2;
    const int warp_n = wid & 3;
    const int nKB    = K >> 5;

    const unsigned* Atile = Ap + (size_t)blockIdx.y * nKB * 4096;
    const unsigned* Btile = Bp + (size_t)blockIdx.x * nKB * 4096;
    const uint32_t sbase = (uint32_t)__cvta_generic_to_shared(smg);

    float acc[4][4][4];
#pragma unroll
    for (int i = 0; i < 4; i++)
#pragma unroll
        for (int j = 0; j < 4; j++)
#pragma unroll
            for (int c = 0; c < 4; c++) acc[i][j][c] = 0.f;

#define ISSUE_TILE(t)                                                          \
    {                                                                          \
        uint32_t st = sbase + ((t) % GSTAGES) * 32768u;                        \
        const unsigned* asrc = Atile + (size_t)(t) * 4096;                     \
        const unsigned* bsrc = Btile + (size_t)(t) * 4096;                     \
        _Pragma("unroll")                                                      \
        for (int j = 0; j < 4; j++) {                                          \
            int c = tid + 256 * j;                                             \
            asm volatile("cp.async.cg.shared.global [%0],[%1],16;\n"           \
                         :: "r"(st + c * 16u), "l"(asrc + c * 4));             \
            asm volatile("cp.async.cg.shared.global [%0],[%1],16;\n"           \
                         :: "r"(st + 16384u + c * 16u), "l"(bsrc + c * 4));    \
        }                                                                      \
        asm volatile("cp.async.commit_group;\n");                              \
    }

    ISSUE_TILE(0);
    ISSUE_TILE(1);

    for (int t = 0; t < nKB; t++) {
        asm volatile("cp.async.wait_group 1;\n");
        __syncthreads();

        if (t + 2 < nKB) {
            ISSUE_TILE(t + 2);
        } else {
            asm volatile("cp.async.commit_group;\n");
        }

        const unsigned* sA = smg + (t % GSTAGES) * 8192;
        const unsigned* sB = sA + 4096;

#pragma unroll
        for (int kt = 0; kt < 4; kt++) {
            const int lx = lane << 2;
            uint4 af[4], bf[2];
#pragma unroll
            for (int mt = 0; mt < 4; mt++)
                af[mt] = *(const uint4*)&sA[(kt * 8 + warp_m * 4 + mt) * 128 + lx];
#pragma unroll
            for (int p = 0; p < 2; p++)
                bf[p] = *(const uint4*)&sB[(kt * 8 + warp_n * 2 + p) * 128 + lx];

#pragma unroll
            for (int mt = 0; mt < 4; mt++) {
#pragma unroll
                for (int nt = 0; nt < 4; nt++) {
                    const uint4& b4 = bf[nt >> 1];
                    unsigned b0 = (nt & 1) ? b4.z : b4.x;
                    unsigned b1 = (nt & 1) ? b4.w : b4.y;
                    mma8(acc[mt][nt], af[mt].x, af[mt].y, af[mt].z, af[mt].w, b0, b1);
                }
            }
        }
    }

    const int m0 = blockIdx.y * 128;
    const int n0 = blockIdx.x * 128;
#pragma unroll
    for (int mt = 0; mt < 4; mt++) {
        int row = m0 + warp_m * 64 + mt * 16 + (lane >> 2);
#pragma unroll
        for (int nt = 0; nt < 4; nt++) {
            int col = n0 + warp_n * 32 + nt * 8 + 2 * (lane & 3);
            float2 bv = *(const float2*)&bias[col];
            float2 o0 = make_float2(acc[mt][nt][0] + bv.x, acc[mt][nt][1] + bv.y);
            float2 o1 = make_float2(acc[mt][nt][2] + bv.x, acc[mt][nt][3] + bv.y);
            *(float2*)&C[(size_t)row * N + col]       = o0;
            *(float2*)&C[(size_t)(row + 8) * N + col] = o1;
        }
    }
#undef ISSUE_TILE
}

// ---------------------------------------------------------------------------
// Fragment packer for attention: qkv -> Q(hi/lo,scaled) A-frags, K(hi/lo)
// B-frags, V^T B-frags. One block per (64-token tile, h, b).
// ---------------------------------------------------------------------------
__global__ __launch_bounds__(256) void frag_pack(const float* __restrict__ qkv)
{
    const int t = blockIdx.x, h = blockIdx.y, b = blockIdx.z;
    const size_t rowbase = (size_t)b * Sc + (size_t)t * 64;
    const size_t obase = ((size_t)(b * Hc + h) * 32 + t) * 1024;  // uint4 idx

#pragma unroll
    for (int i = 0; i < 4; i++) {
        int u = threadIdx.x + 256 * i;
        int lane = u & 31, sub = (u >> 5) & 3, kd = u >> 7;
        int r0 = sub * 16 + (lane >> 2);
        int c0 = kd * 8 + (lane & 3);

        const float* base0 = qkv + (rowbase + r0) * 3072 + h * 64;
        const float* base8 = base0 + (size_t)8 * 3072;

        // ---- Q (scaled by 0.125, hi/lo split) ----
        float q00 = base0[c0] * 0.125f, q01 = base0[c0 + 4] * 0.125f;
        float q10 = base8[c0] * 0.125f, q11 = base8[c0 + 4] * 0.125f;
        uint4 qh, ql;
        qh.x = f2tf32(q00); ql.x = f2tf32(q00 - __uint_as_float(qh.x));
        qh.y = f2tf32(q10); ql.y = f2tf32(q10 - __uint_as_float(qh.y));
        qh.z = f2tf32(q01); ql.z = f2tf32(q01 - __uint_as_float(qh.z));
        qh.w = f2tf32(q11); ql.w = f2tf32(q11 - __uint_as_float(qh.w));
        ((uint4*)g_qfh)[obase + u] = qh;
        ((uint4*)g_qfl)[obase + u] = ql;

        // ---- K (hi/lo): B-slots x=(n0,c0) y=(n0,c0+4) z=(n0+8,c0) w=(n0+8,c0+4)
        float k00 = base0[1024 + c0], k01 = base0[1024 + c0 + 4];
        float k10 = base8[1024 + c0], k11 = base8[1024 + c0 + 4];
        uint4 kh, kl;
        kh.x = f2tf32(k00); kl.x = f2tf32(k00 - __uint_as_float(kh.x));
        kh.y = f2tf32(k01); kl.y = f2tf32(k01 - __uint_as_float(kh.y));
        kh.z = f2tf32(k10); kl.z = f2tf32(k10 - __uint_as_float(kh.z));
        kh.w = f2tf32(k11); kl.w = f2tf32(k11 - __uint_as_float(kh.w));
        ((uint4*)g_kfh)[obase + u] = kh;
        ((uint4*)g_kfl)[obase + u] = kl;

        // ---- V^T: (n=dim r0, k=key c0): x=V[c0][n0] y=V[c0+4][n0] z,w at n0+8
        const float* vb0 = qkv + (rowbase + c0) * 3072 + 2048 + h * 64;
        const float* vb4 = vb0 + (size_t)4 * 3072;
        uint4 vv;
        vv.x = f2tf32(vb0[r0]);
        vv.y = f2tf32(vb4[r0]);
        vv.z = f2tf32(vb0[r0 + 8]);
        vv.w = f2tf32(vb4[r0 + 8]);
        ((uint4*)g_vf)[obase + u] = vv;
    }
}

// ---------------------------------------------------------------------------
// Tensor-core windowed attention. Block = (b,h,qtile64), 4 warps.
// S via 3xTF32 (hi/lo Q,K), online softmax in regs, PV via plain tf32.
// Writes output directly in out-proj A-fragment layout.
// ---------------------------------------------------------------------------
__device__ __forceinline__ void storeAfrag(unsigned* P, int q, int col, unsigned v) {
    int mblk = q >> 7, mtg = (q >> 4) & 7, rr = q & 15;
    int kblk = col >> 5, kt = (col >> 3) & 3;
    int lanep = (rr & 7) * 4 + (col & 3);
    int slot  = (rr >> 3) + 2 * ((col >> 2) & 1);
    P[(size_t)(mblk * 32 + kblk) * 4096 + kt * 1024 + mtg * 128 + lanep * 4 + slot] = v;
}

__global__ __launch_bounds__(128) void attn_mma(unsigned* __restrict__ Operm)
{
    extern __shared__ unsigned sm[];
    // words: buf p @ p*12288 (Kh 4096 | Kl 4096 | V 4096); sP @ 24576 (4*16*66)
    const int tid = threadIdx.x, lane = tid & 31, wid = tid >> 5;
    const int qt = blockIdx.x, h = blockIdx.y, b = blockIdx.z;
    const int bh = b * Hc + h;
    const uint32_t sbase = (uint32_t)__cvta_generic_to_shared(sm);

    // --- Q staging (into buf0 region), then to regs ---
    {
        const unsigned* qh_ = g_qfh + ((size_t)bh * 32 + qt) * 4096;
        const unsigned* ql_ = g_qfl + ((size_t)bh * 32 + qt) * 4096;
#pragma unroll
        for (int j = 0; j < 8; j++) {
            int c = tid + 128 * j;
            asm volatile("cp.async.cg.shared.global [%0],[%1],16;"
                         :: "r"(sbase + c * 16u), "l"(qh_ + c * 4));
            asm volatile("cp.async.cg.shared.global [%0],[%1],16;"
                         :: "r"(sbase + 16384u + c * 16u), "l"(ql_ + c * 4));
        }
        asm volatile("cp.async.commit_group;");
        asm volatile("cp.async.wait_group 0;");
    }
    __syncthreads();
    uint4 qh[8], ql[8];
#pragma unroll
    for (int kd = 0; kd < 8; kd++) {
        qh[kd] = *(const uint4*)&sm[(kd * 4 + wid) * 128 + lane * 4];
        ql[kd] = *(const uint4*)&sm[4096 + (kd * 4 + wid) * 128 + lane * 4];
    }
    __syncthreads();

    const int ktlo = (qt - 2 > 0) ? qt - 2 : 0;
    const int kthi = (qt + 2 < 31) ? qt + 2 : 31;
    const int nT = kthi - ktlo + 1;

#define ISSUE_KV(kt, p)                                                         \
    {                                                                           \
        const unsigned* kh_ = g_kfh + ((size_t)bh * 32 + (kt)) * 4096;          \
        const unsigned* kl_ = g_kfl + ((size_t)bh * 32 + (kt)) * 4096;          \
        const unsigned* v_  = g_vf  + ((size_t)bh * 32 + (kt)) * 4096;          \
        uint32_t dst = sbase + (p) * 49152u;                                    \
        _Pragma("unroll")                                                       \
        for (int j = 0; j < 8; j++) {                                           \
            int c = tid + 128 * j;                                              \
            asm volatile("cp.async.cg.shared.global [%0],[%1],16;"              \
                         :: "r"(dst + c * 16u), "l"(kh_ + c * 4));              \
            asm volatile("cp.async.cg.shared.global [%0],[%1],16;"              \
                         :: "r"(dst + 16384u + c * 16u), "l"(kl_ + c * 4));     \
            asm volatile("cp.async.cg.shared.global [%0],[%1],16;"              \
                         :: "r"(dst + 32768u + c * 16u), "l"(v_ + c * 4));      \
        }                                                                       \
        asm volatile("cp.async.commit_group;");                                 \
    }

    ISSUE_KV(ktlo, 0);
    ISSUE_KV(ktlo + 1, 1);

    float o[8][4];
#pragma unroll
    for (int i = 0; i < 8; i++)
#pragma unroll
        for (int c = 0; c < 4; c++) o[i][c] = 0.f;
    float mA = -1e30f, mB = -1e30f, lA = 0.f, lB = 0.f;

    unsigned* sP = sm + 24576 + wid * 1056;   // 16 x 66

    for (int j = 0; j < nT; j++) {
        const int kt = ktlo + j, p = j & 1;
        asm volatile("cp.async.wait_group 1;");
        __syncthreads();

        const unsigned* bKh = sm + p * 12288;
        const unsigned* bKl = bKh + 4096;
        const unsigned* bV  = bKh + 8192;

        // ---- S = Q K^T (3xTF32) ----
        float s[8][4];
#pragma unroll
        for (int i = 0; i < 8; i++)
#pragma unroll
            for (int c = 0; c < 4; c++) s[i][c] = 0.f;

#pragma unroll
        for (int kd = 0; kd < 8; kd++) {
            uint4 kh4[4], kl4[4];
#pragma unroll
            for (int ntp = 0; ntp < 4; ntp++) {
                kh4[ntp] = *(const uint4*)&bKh[(kd * 4 + ntp) * 128 + lane * 4];
                kl4[ntp] = *(const uint4*)&bKl[(kd * 4 + ntp) * 128 + lane * 4];
            }
#pragma unroll
            for (int ntp = 0; ntp < 4; ntp++) {
#pragma unroll
                for (int e = 0; e < 2; e++) {
                    unsigned bh0 = e ? kh4[ntp].z : kh4[ntp].x;
                    unsigned bh1 = e ? kh4[ntp].w : kh4[ntp].y;
                    unsigned bl0 = e ? kl4[ntp].z : kl4[ntp].x;
                    unsigned bl1 = e ? kl4[ntp].w : kl4[ntp].y;
                    float* c = s[ntp * 2 + e];
                    mma8(c, qh[kd].x, qh[kd].y, qh[kd].z, qh[kd].w, bh0, bh1);
                    mma8(c, ql[kd].x, ql[kd].y, ql[kd].z, ql[kd].w, bh0, bh1);
                    mma8(c, qh[kd].x, qh[kd].y, qh[kd].z, qh[kd].w, bl0, bl1);
                }
            }
        }

        // ---- banded mask (only outermost tiles are partial) ----
        if (kt - qt == 2 || qt - kt == 2) {
            int q1 = qt * 64 + wid * 16 + (lane >> 2);
            int k00 = kt * 64 + 2 * (lane & 3);
#pragma unroll
            for (int nt = 0; nt < 8; nt++) {
#pragma unroll
                for (int ci = 0; ci < 4; ci++) {
                    int qv = q1 + ((ci >= 2) ? 8 : 0);
                    int kv = k00 + nt * 8 + (ci & 1);
                    int d = qv - kv; d = (d < 0) ? -d : d;
                    if (d > Wc) s[nt][ci] = -1e30f;
                }
            }
        }

        // ---- online softmax ----
        float tA = -1e30f, tB = -1e30f;
#pragma unroll
        for (int nt = 0; nt < 8; nt++) {
            tA = fmaxf(tA, fmaxf(s[nt][0], s[nt][1]));
            tB = fmaxf(tB, fmaxf(s[nt][2], s[nt][3]));
        }
        tA = fmaxf(tA, __shfl_xor_sync(0xffffffffu, tA, 1));
        tA = fmaxf(tA, __shfl_xor_sync(0xffffffffu, tA, 2));
        tB = fmaxf(tB, __shfl_xor_sync(0xffffffffu, tB, 1));
        tB = fmaxf(tB, __shfl_xor_sync(0xffffffffu, tB, 2));
        float mnA = fmaxf(mA, tA), mnB = fmaxf(mB, tB);
        float aA = __expf(mA - mnA), aB = __expf(mB - mnB);
        mA = mnA; mB = mnB;
        float sumA = 0.f, sumB = 0.f;
#pragma unroll
        for (int nt = 0; nt < 8; nt++) {
            s[nt][0] = __expf(s[nt][0] - mnA);
            s[nt][1] = __expf(s[nt][1] - mnA);
            s[nt][2] = __expf(s[nt][2] - mnB);
            s[nt][3] = __expf(s[nt][3] - mnB);
            sumA += s[nt][0] + s[nt][1];
            sumB += s[nt][2] + s[nt][3];
        }
        sumA += __shfl_xor_sync(0xffffffffu, sumA, 1);
        sumA += __shfl_xor_sync(0xffffffffu, sumA, 2);
        sumB += __shfl_xor_sync(0xffffffffu, sumB, 1);
        sumB += __shfl_xor_sync(0xffffffffu, sumB, 2);
        lA = lA * aA + sumA;
        lB = lB * aB + sumB;
#pragma unroll
        for (int nt = 0; nt < 8; nt++) {
            o[nt][0] *= aA; o[nt][1] *= aA;
            o[nt][2] *= aB; o[nt][3] *= aB;
        }

        // ---- stage P (warp-private) ----
        {
            int rA = lane >> 2, cb = 2 * (lane & 3);
#pragma unroll
            for (int nt = 0; nt < 8; nt++) {
                int c = nt * 8 + cb;
                uint2 v0 = make_uint2(f2tf32(s[nt][0]), f2tf32(s[nt][1]));
                uint2 v1 = make_uint2(f2tf32(s[nt][2]), f2tf32(s[nt][3]));
                *(uint2*)&sP[rA * 66 + c]       = v0;
                *(uint2*)&sP[(rA + 8) * 66 + c] = v1;
            }
        }
        __syncwarp();

        // ---- O += P V ----
#pragma unroll
        for (int kk = 0; kk < 8; kk++) {
            int rA = lane >> 2, cA = kk * 8 + (lane & 3);
            unsigned a0 = sP[rA * 66 + cA];
            unsigned a1 = sP[(rA + 8) * 66 + cA];
            unsigned a2 = sP[rA * 66 + cA + 4];
            unsigned a3 = sP[(rA + 8) * 66 + cA + 4];
            uint4 v4[4];
#pragma unroll
            for (int ntp = 0; ntp < 4; ntp++)
                v4[ntp] = *(const uint4*)&bV[(kk * 4 + ntp) * 128 + lane * 4];
#pragma unroll
            for (int ntp = 0; ntp < 4; ntp++) {
#pragma unroll
                for (int e = 0; e < 2; e++) {
                    unsigned b0 = e ? v4[ntp].z : v4[ntp].x;
                    unsigned b1 = e ? v4[ntp].w : v4[ntp].y;
                    mma8(o[ntp * 2 + e], a0, a1, a2, a3, b0, b1);
                }
            }
        }
        __syncthreads();

        if (kt + 2 <= kthi) {
            ISSUE_KV(kt + 2, p);
        } else {
            asm volatile("cp.async.commit_group;");
        }
    }

    // ---- epilogue: normalize, write in out-proj A-fragment layout ----
    float iA = 1.f / lA, iB = 1.f / lB;
    int qg = b * Sc + qt * 64 + wid * 16 + (lane >> 2);
#pragma unroll
    for (int nt = 0; nt < 8; nt++) {
#pragma unroll
        for (int j2 = 0; j2 < 2; j2++) {
            int col = h * 64 + nt * 8 + 2 * (lane & 3) + j2;
            storeAfrag(Operm, qg,     col, f2tf32(o[nt][j2] * iA));
            storeAfrag(Operm, qg + 8, col, f2tf32(o[nt][2 + j2] * iB));
        }
    }
#undef ISSUE_KV
}

// ---------------------------------------------------------------------------
extern "C" void kernel_launch(void* const* d_in, const int* in_sizes, int n_in,
                              void* d_out, int out_size)
{
    (void)in_sizes; (void)n_in; (void)out_size;
    const float* x     = (const float*)d_in[0];
    const float* in_w  = (const float*)d_in[1];
    const float* in_b  = (const float*)d_in[2];
    const float* out_w = (const float*)d_in[3];
    const float* out_b = (const float*)d_in[4];
    float* out = (float*)d_out;

    float* qkv;
    unsigned *xp, *ap, *wqp, *wop;
    cudaGetSymbolAddress((void**)&qkv, g_qkv);
    cudaGetSymbolAddress((void**)&xp,  g_xperm);
    cudaGetSymbolAddress((void**)&ap,  g_attnperm);
    cudaGetSymbolAddress((void**)&wqp, g_wqkvperm);
    cudaGetSymbolAddress((void**)&wop, g_woutperm);

    const int M = Bc * Sc;                      // 4096
    const int smem_gemm = GSTAGES * 32768;      // 96 KB
    const int smem_attn = 28800 * 4;            // 115200 B
    cudaFuncSetAttribute(gemm_tf32p,
                         cudaFuncAttributeMaxDynamicSharedMemorySize, smem_gemm);
    cudaFuncSetAttribute(attn_mma,
                         cudaFuncAttributeMaxDynamicSharedMemorySize, smem_attn);

    // Operand packers for projections
    permA<<<(M * Dc / 4 + 255) / 256, 256>>>(x, xp, M, Dc);
    permB<<<(3 * Dc * Dc / 4 + 255) / 256, 256>>>(in_w, wqp, 3 * Dc, Dc);
    permB<<<(Dc * Dc / 4 + 255) / 256, 256>>>(out_w, wop, Dc, Dc);

    // 1) QKV projection
    gemm_tf32p<<<dim3(3 * Dc / 128, M / 128), 256, smem_gemm>>>(
        xp, wqp, in_b, qkv, M, 3 * Dc, Dc);

    // 2) Pack attention fragments, run tensor-core attention
    frag_pack<<<dim3(Sc / 64, Hc, Bc), 256>>>(qkv);
    attn_mma<<<dim3(Sc / 64, Hc, Bc), 128, smem_attn>>>(ap);

    // 3) Output projection (consumes A-fragment layout written by attention)
    gemm_tf32p<<<dim3(Dc / 128, M / 128), 256, smem_gemm>>>(
        ap, wop, out_b, out, M, Dc, Dc);
}

// round 8
// speedup vs baseline: 3.8871x; 1.0248x over previous
#include <cuda_runtime.h>
#include <cstdint>

// Problem constants
#define Bc   2
#define Sc   2048
#define Dc   1024
#define Hc   16
#define HDc  64
#define Wc   128

// Scratch (allocation-free rule: __device__ globals)
__device__ float    g_qkv[Bc * Sc * 3 * Dc];    // [B,S,3D]
__device__ unsigned g_xperm[Bc * Sc * Dc];      // x in A-fragment layout (tf32)
__device__ unsigned g_attnperm[Bc * Sc * Dc];   // attn out in A-fragment layout
__device__ unsigned g_wqkvperm[3 * Dc * Dc];    // in_proj_w in B-fragment layout
__device__ unsigned g_woutperm[Dc * Dc];        // out_proj_w in B-fragment layout
// Attention fragment buffers (per (b,h,tile64): 4096 words)
__device__ unsigned g_qfh[Bc * Sc * Dc];        // Q A-frag hi (scaled)
__device__ unsigned g_qfl[Bc * Sc * Dc];        // Q A-frag lo
__device__ unsigned g_kfh[Bc * Sc * Dc];        // K B-frag hi
__device__ unsigned g_kfl[Bc * Sc * Dc];        // K B-frag lo
__device__ unsigned g_vf [Bc * Sc * Dc];        // V^T B-frag (n=dim,k=key)

__device__ __forceinline__ unsigned f2tf32(float x) {
    unsigned r;
    asm("cvt.rna.tf32.f32 %0, %1;" : "=r"(r) : "f"(x));
    return r;
}

__device__ __forceinline__ void mma8(float* c, unsigned a0, unsigned a1,
                                     unsigned a2, unsigned a3,
                                     unsigned b0, unsigned b1) {
    asm volatile(
        "mma.sync.aligned.m16n8k8.row.col.f32.tf32.tf32.f32 "
        "{%0,%1,%2,%3}, {%4,%5,%6,%7}, {%8,%9}, {%0,%1,%2,%3};\n"
        : "+f"(c[0]), "+f"(c[1]), "+f"(c[2]), "+f"(c[3])
        : "r"(a0), "r"(a1), "r"(a2), "r"(a3), "r"(b0), "r"(b1));
}

// Swizzled P-staging address: 16x64 words, XOR kills the 8-way bank conflict.
#define SWP(r, c) ((r) * 64 + ((c) ^ (((r) & 3) << 3)))

// ---------------------------------------------------------------------------
// permA / permB: projection-GEMM operand packers (unchanged, proven)
// ---------------------------------------------------------------------------
__global__ __launch_bounds__(256) void permA(
    const float* __restrict__ X, unsigned* __restrict__ P, int M, int K)
{
    int idx = blockIdx.x * blockDim.x + threadIdx.x;
    int total = (M * K) >> 2;
    if (idx >= total) return;
    int nKB  = K >> 5;
    int lane = idx & 31;
    int mtg  = (idx >> 5) & 7;
    int kt   = (idx >> 8) & 3;
    int rest = idx >> 10;
    int kblk = rest % nKB;
    int mblk = rest / nKB;
    int r0 = mblk * 128 + mtg * 16 + (lane >> 2);
    int c0 = kblk * 32 + kt * 8 + (lane & 3);
    const float* x = X + (size_t)r0 * K + c0;
    uint4 v;
    v.x = f2tf32(x[0]);
    v.y = f2tf32(x[(size_t)8 * K]);
    v.z = f2tf32(x[4]);
    v.w = f2tf32(x[(size_t)8 * K + 4]);
    ((uint4*)P)[idx] = v;
}

__global__ __launch_bounds__(256) void permB(
    const float* __restrict__ X, unsigned* __restrict__ P, int N, int K)
{
    int idx = blockIdx.x * blockDim.x + threadIdx.x;
    int total = (N * K) >> 2;
    if (idx >= total) return;
    int nKB  = K >> 5;
    int lane = idx & 31;
    int ntp  = (idx >> 5) & 7;
    int kt   = (idx >> 8) & 3;
    int rest = idx >> 10;
    int kblk = rest % nKB;
    int nblk = rest / nKB;
    int n0 = nblk * 128 + ntp * 16 + (lane >> 2);
    int c0 = kblk * 32 + kt * 8 + (lane & 3);
    const float* x = X + (size_t)n0 * K + c0;
    uint4 v;
    v.x = f2tf32(x[0]);
    v.y = f2tf32(x[4]);
    v.z = f2tf32(x[(size_t)8 * K]);
    v.w = f2tf32(x[(size_t)8 * K + 4]);
    ((uint4*)P)[idx] = v;
}

// ---------------------------------------------------------------------------
// Projection GEMM on pre-permuted operands (unchanged, proven).
// ---------------------------------------------------------------------------
#define GSTAGES 3
__global__ __launch_bounds__(256, 2) void gemm_tf32p(
    const unsigned* __restrict__ Ap, const unsigned* __restrict__ Bp,
    const float* __restrict__ bias, float* __restrict__ C,
    int M, int N, int K)
{
    extern __shared__ unsigned smg[];

    const int tid    = threadIdx.x;
    const int lane   = tid & 31;
    const int wid    = tid >> 5;
    const int warp_m = wid >> 2;
    const int warp_n = wid & 3;
    const int nKB    = K >> 5;

    const unsigned* Atile = Ap + (size_t)blockIdx.y * nKB * 4096;
    const unsigned* Btile = Bp + (size_t)blockIdx.x * nKB * 4096;
    const uint32_t sbase = (uint32_t)__cvta_generic_to_shared(smg);

    float acc[4][4][4];
#pragma unroll
    for (int i = 0; i < 4; i++)
#pragma unroll
        for (int j = 0; j < 4; j++)
#pragma unroll
            for (int c = 0; c < 4; c++) acc[i][j][c] = 0.f;

#define ISSUE_TILE(t)                                                          \
    {                                                                          \
        uint32_t st = sbase + ((t) % GSTAGES) * 32768u;                        \
        const unsigned* asrc = Atile + (size_t)(t) * 4096;                     \
        const unsigned* bsrc = Btile + (size_t)(t) * 4096;                     \
        _Pragma("unroll")                                                      \
        for (int j = 0; j < 4; j++) {                                          \
            int c = tid + 256 * j;                                             \
            asm volatile("cp.async.cg.shared.global [%0],[%1],16;\n"           \
                         :: "r"(st + c * 16u), "l"(asrc + c * 4));             \
            asm volatile("cp.async.cg.shared.global [%0],[%1],16;\n"           \
                         :: "r"(st + 16384u + c * 16u), "l"(bsrc + c * 4));    \
        }                                                                      \
        asm volatile("cp.async.commit_group;\n");                              \
    }

    ISSUE_TILE(0);
    ISSUE_TILE(1);

    for (int t = 0; t < nKB; t++) {
        asm volatile("cp.async.wait_group 1;\n");
        __syncthreads();

        if (t + 2 < nKB) {
            ISSUE_TILE(t + 2);
        } else {
            asm volatile("cp.async.commit_group;\n");
        }

        const unsigned* sA = smg + (t % GSTAGES) * 8192;
        const unsigned* sB = sA + 4096;

#pragma unroll
        for (int kt = 0; kt < 4; kt++) {
            const int lx = lane << 2;
            uint4 af[4], bf[2];
#pragma unroll
            for (int mt = 0; mt < 4; mt++)
                af[mt] = *(const uint4*)&sA[(kt * 8 + warp_m * 4 + mt) * 128 + lx];
#pragma unroll
            for (int p = 0; p < 2; p++)
                bf[p] = *(const uint4*)&sB[(kt * 8 + warp_n * 2 + p) * 128 + lx];

#pragma unroll
            for (int mt = 0; mt < 4; mt++) {
#pragma unroll
                for (int nt = 0; nt < 4; nt++) {
                    const uint4& b4 = bf[nt >> 1];
                    unsigned b0 = (nt & 1) ? b4.z : b4.x;
                    unsigned b1 = (nt & 1) ? b4.w : b4.y;
                    mma8(acc[mt][nt], af[mt].x, af[mt].y, af[mt].z, af[mt].w, b0, b1);
                }
            }
        }
    }

    const int m0 = blockIdx.y * 128;
    const int n0 = blockIdx.x * 128;
#pragma unroll
    for (int mt = 0; mt < 4; mt++) {
        int row = m0 + warp_m * 64 + mt * 16 + (lane >> 2);
#pragma unroll
        for (int nt = 0; nt < 4; nt++) {
            int col = n0 + warp_n * 32 + nt * 8 + 2 * (lane & 3);
            float2 bv = *(const float2*)&bias[col];
            float2 o0 = make_float2(acc[mt][nt][0] + bv.x, acc[mt][nt][1] + bv.y);
            float2 o1 = make_float2(acc[mt][nt][2] + bv.x, acc[mt][nt][3] + bv.y);
            *(float2*)&C[(size_t)row * N + col]       = o0;
            *(float2*)&C[(size_t)(row + 8) * N + col] = o1;
        }
    }
#undef ISSUE_TILE
}

// ---------------------------------------------------------------------------
// Fragment packer for attention (unchanged, proven).
// ---------------------------------------------------------------------------
__global__ __launch_bounds__(256) void frag_pack(const float* __restrict__ qkv)
{
    const int t = blockIdx.x, h = blockIdx.y, b = blockIdx.z;
    const size_t rowbase = (size_t)b * Sc + (size_t)t * 64;
    const size_t obase = ((size_t)(b * Hc + h) * 32 + t) * 1024;  // uint4 idx

#pragma unroll
    for (int i = 0; i < 4; i++) {
        int u = threadIdx.x + 256 * i;
        int lane = u & 31, sub = (u >> 5) & 3, kd = u >> 7;
        int r0 = sub * 16 + (lane >> 2);
        int c0 = kd * 8 + (lane & 3);

        const float* base0 = qkv + (rowbase + r0) * 3072 + h * 64;
        const float* base8 = base0 + (size_t)8 * 3072;

        float q00 = base0[c0] * 0.125f, q01 = base0[c0 + 4] * 0.125f;
        float q10 = base8[c0] * 0.125f, q11 = base8[c0 + 4] * 0.125f;
        uint4 qh, ql;
        qh.x = f2tf32(q00); ql.x = f2tf32(q00 - __uint_as_float(qh.x));
        qh.y = f2tf32(q10); ql.y = f2tf32(q10 - __uint_as_float(qh.y));
        qh.z = f2tf32(q01); ql.z = f2tf32(q01 - __uint_as_float(qh.z));
        qh.w = f2tf32(q11); ql.w = f2tf32(q11 - __uint_as_float(qh.w));
        ((uint4*)g_qfh)[obase + u] = qh;
        ((uint4*)g_qfl)[obase + u] = ql;

        float k00 = base0[1024 + c0], k01 = base0[1024 + c0 + 4];
        float k10 = base8[1024 + c0], k11 = base8[1024 + c0 + 4];
        uint4 kh, kl;
        kh.x = f2tf32(k00); kl.x = f2tf32(k00 - __uint_as_float(kh.x));
        kh.y = f2tf32(k01); kl.y = f2tf32(k01 - __uint_as_float(kh.y));
        kh.z = f2tf32(k10); kl.z = f2tf32(k10 - __uint_as_float(kh.z));
        kh.w = f2tf32(k11); kl.w = f2tf32(k11 - __uint_as_float(kh.w));
        ((uint4*)g_kfh)[obase + u] = kh;
        ((uint4*)g_kfl)[obase + u] = kl;

        const float* vb0 = qkv + (rowbase + c0) * 3072 + 2048 + h * 64;
        const float* vb4 = vb0 + (size_t)4 * 3072;
        uint4 vv;
        vv.x = f2tf32(vb0[r0]);
        vv.y = f2tf32(vb4[r0]);
        vv.z = f2tf32(vb0[r0 + 8]);
        vv.w = f2tf32(vb4[r0 + 8]);
        ((uint4*)g_vf)[obase + u] = vv;
    }
}

// ---------------------------------------------------------------------------
// Tensor-core windowed attention. Block = (b,h,qtile64), 4 warps.
// S via 3xTF32, online softmax in regs, PV via plain tf32.
// Smem = 112 KB exactly -> 2 CTAs/SM (8 warps/SM).
// ---------------------------------------------------------------------------
__device__ __forceinline__ void storeAfrag(unsigned* P, int q, int col, unsigned v) {
    int mblk = q >> 7, mtg = (q >> 4) & 7, rr = q & 15;
    int kblk = col >> 5, kt = (col >> 3) & 3;
    int lanep = (rr & 7) * 4 + (col & 3);
    int slot  = (rr >> 3) + 2 * ((col >> 2) & 1);
    P[(size_t)(mblk * 32 + kblk) * 4096 + kt * 1024 + mtg * 128 + lanep * 4 + slot] = v;
}

__global__ __launch_bounds__(128, 2) void attn_mma(unsigned* __restrict__ Operm)
{
    extern __shared__ unsigned sm[];
    // words: buf p @ p*12288 (Kh 4096 | Kl 4096 | V 4096); sP @ 24576 (4*1024)
    const int tid = threadIdx.x, lane = tid & 31, wid = tid >> 5;
    const int qt = blockIdx.x, h = blockIdx.y, b = blockIdx.z;
    const int bh = b * Hc + h;
    const uint32_t sbase = (uint32_t)__cvta_generic_to_shared(sm);

    // --- Q staging (into buf0 region), then to regs ---
    {
        const unsigned* qh_ = g_qfh + ((size_t)bh * 32 + qt) * 4096;
        const unsigned* ql_ = g_qfl + ((size_t)bh * 32 + qt) * 4096;
#pragma unroll
        for (int j = 0; j < 8; j++) {
            int c = tid + 128 * j;
            asm volatile("cp.async.cg.shared.global [%0],[%1],16;"
                         :: "r"(sbase + c * 16u), "l"(qh_ + c * 4));
            asm volatile("cp.async.cg.shared.global [%0],[%1],16;"
                         :: "r"(sbase + 16384u + c * 16u), "l"(ql_ + c * 4));
        }
        asm volatile("cp.async.commit_group;");
        asm volatile("cp.async.wait_group 0;");
    }
    __syncthreads();
    uint4 qh[8], ql[8];
#pragma unroll
    for (int kd = 0; kd < 8; kd++) {
        qh[kd] = *(const uint4*)&sm[(kd * 4 + wid) * 128 + lane * 4];
        ql[kd] = *(const uint4*)&sm[4096 + (kd * 4 + wid) * 128 + lane * 4];
    }
    __syncthreads();

    const int ktlo = (qt - 2 > 0) ? qt - 2 : 0;
    const int kthi = (qt + 2 < 31) ? qt + 2 : 31;
    const int nT = kthi - ktlo + 1;

#define ISSUE_KV(kt, p)                                                         \
    {                                                                           \
        const unsigned* kh_ = g_kfh + ((size_t)bh * 32 + (kt)) * 4096;          \
        const unsigned* kl_ = g_kfl + ((size_t)bh * 32 + (kt)) * 4096;          \
        const unsigned* v_  = g_vf  + ((size_t)bh * 32 + (kt)) * 4096;          \
        uint32_t dst = sbase + (p) * 49152u;                                    \
        _Pragma("unroll")                                                       \
        for (int j = 0; j < 8; j++) {                                           \
            int c = tid + 128 * j;                                              \
            asm volatile("cp.async.cg.shared.global [%0],[%1],16;"              \
                         :: "r"(dst + c * 16u), "l"(kh_ + c * 4));              \
            asm volatile("cp.async.cg.shared.global [%0],[%1],16;"              \
                         :: "r"(dst + 16384u + c * 16u), "l"(kl_ + c * 4));     \
            asm volatile("cp.async.cg.shared.global [%0],[%1],16;"              \
                         :: "r"(dst + 32768u + c * 16u), "l"(v_ + c * 4));      \
        }                                                                       \
        asm volatile("cp.async.commit_group;");                                 \
    }

    ISSUE_KV(ktlo, 0);
    ISSUE_KV(ktlo + 1, 1);

    float o[8][4];
#pragma unroll
    for (int i = 0; i < 8; i++)
#pragma unroll
        for (int c = 0; c < 4; c++) o[i][c] = 0.f;
    float mA = -1e30f, mB = -1e30f, lA = 0.f, lB = 0.f;

    unsigned* sP = sm + 24576 + wid * 1024;   // 16 x 64, SWP-swizzled

    for (int j = 0; j < nT; j++) {
        const int kt = ktlo + j, p = j & 1;
        asm volatile("cp.async.wait_group 1;");
        __syncthreads();

        const unsigned* bKh = sm + p * 12288;
        const unsigned* bKl = bKh + 4096;
        const unsigned* bV  = bKh + 8192;

        // ---- S = Q K^T (3xTF32) ----
        float s[8][4];
#pragma unroll
        for (int i = 0; i < 8; i++)
#pragma unroll
            for (int c = 0; c < 4; c++) s[i][c] = 0.f;

#pragma unroll
        for (int kd = 0; kd < 8; kd++) {
            uint4 kh4[4], kl4[4];
#pragma unroll
            for (int ntp = 0; ntp < 4; ntp++) {
                kh4[ntp] = *(const uint4*)&bKh[(kd * 4 + ntp) * 128 + lane * 4];
                kl4[ntp] = *(const uint4*)&bKl[(kd * 4 + ntp) * 128 + lane * 4];
            }
#pragma unroll
            for (int ntp = 0; ntp < 4; ntp++) {
#pragma unroll
                for (int e = 0; e < 2; e++) {
                    unsigned bh0 = e ? kh4[ntp].z : kh4[ntp].x;
                    unsigned bh1 = e ? kh4[ntp].w : kh4[ntp].y;
                    unsigned bl0 = e ? kl4[ntp].z : kl4[ntp].x;
                    unsigned bl1 = e ? kl4[ntp].w : kl4[ntp].y;
                    float* c = s[ntp * 2 + e];
                    mma8(c, qh[kd].x, qh[kd].y, qh[kd].z, qh[kd].w, bh0, bh1);
                    mma8(c, ql[kd].x, ql[kd].y, ql[kd].z, ql[kd].w, bh0, bh1);
                    mma8(c, qh[kd].x, qh[kd].y, qh[kd].z, qh[kd].w, bl0, bl1);
                }
            }
        }

        // ---- banded mask (only outermost tiles are partial) ----
        if (kt - qt == 2 || qt - kt == 2) {
            int q1 = qt * 64 + wid * 16 + (lane >> 2);
            int k00 = kt * 64 + 2 * (lane & 3);
#pragma unroll
            for (int nt = 0; nt < 8; nt++) {
#pragma unroll
                for (int ci = 0; ci < 4; ci++) {
                    int qv = q1 + ((ci >= 2) ? 8 : 0);
                    int kv = k00 + nt * 8 + (ci & 1);
                    int d = qv - kv; d = (d < 0) ? -d : d;
                    if (d > Wc) s[nt][ci] = -1e30f;
                }
            }
        }

        // ---- online softmax ----
        float tA = -1e30f, tB = -1e30f;
#pragma unroll
        for (int nt = 0; nt < 8; nt++) {
            tA = fmaxf(tA, fmaxf(s[nt][0], s[nt][1]));
            tB = fmaxf(tB, fmaxf(s[nt][2], s[nt][3]));
        }
        tA = fmaxf(tA, __shfl_xor_sync(0xffffffffu, tA, 1));
        tA = fmaxf(tA, __shfl_xor_sync(0xffffffffu, tA, 2));
        tB = fmaxf(tB, __shfl_xor_sync(0xffffffffu, tB, 1));
        tB = fmaxf(tB, __shfl_xor_sync(0xffffffffu, tB, 2));
        float mnA = fmaxf(mA, tA), mnB = fmaxf(mB, tB);
        float aA = __expf(mA - mnA), aB = __expf(mB - mnB);
        mA = mnA; mB = mnB;
        float sumA = 0.f, sumB = 0.f;
#pragma unroll
        for (int nt = 0; nt < 8; nt++) {
            s[nt][0] = __expf(s[nt][0] - mnA);
            s[nt][1] = __expf(s[nt][1] - mnA);
            s[nt][2] = __expf(s[nt][2] - mnB);
            s[nt][3] = __expf(s[nt][3] - mnB);
            sumA += s[nt][0] + s[nt][1];
            sumB += s[nt][2] + s[nt][3];
        }
        sumA += __shfl_xor_sync(0xffffffffu, sumA, 1);
        sumA += __shfl_xor_sync(0xffffffffu, sumA, 2);
        sumB += __shfl_xor_sync(0xffffffffu, sumB, 1);
        sumB += __shfl_xor_sync(0xffffffffu, sumB, 2);
        lA = lA * aA + sumA;
        lB = lB * aB + sumB;
#pragma unroll
        for (int nt = 0; nt < 8; nt++) {
            o[nt][0] *= aA; o[nt][1] *= aA;
            o[nt][2] *= aB; o[nt][3] *= aB;
        }

        // ---- stage P (warp-private, swizzled 16x64) ----
        {
            int rA = lane >> 2, cb = 2 * (lane & 3);
#pragma unroll
            for (int nt = 0; nt < 8; nt++) {
                int c = nt * 8 + cb;
                uint2 v0 = make_uint2(f2tf32(s[nt][0]), f2tf32(s[nt][1]));
                uint2 v1 = make_uint2(f2tf32(s[nt][2]), f2tf32(s[nt][3]));
                *(uint2*)&sP[SWP(rA, c)]     = v0;
                *(uint2*)&sP[SWP(rA + 8, c)] = v1;
            }
        }
        __syncwarp();

        // ---- O += P V ----
#pragma unroll
        for (int kk = 0; kk < 8; kk++) {
            int rA = lane >> 2, cA = kk * 8 + (lane & 3);
            unsigned a0 = sP[SWP(rA, cA)];
            unsigned a1 = sP[SWP(rA + 8, cA)];
            unsigned a2 = sP[SWP(rA, cA + 4)];
            unsigned a3 = sP[SWP(rA + 8, cA + 4)];
            uint4 v4[4];
#pragma unroll
            for (int ntp = 0; ntp < 4; ntp++)
                v4[ntp] = *(const uint4*)&bV[(kk * 4 + ntp) * 128 + lane * 4];
#pragma unroll
            for (int ntp = 0; ntp < 4; ntp++) {
#pragma unroll
                for (int e = 0; e < 2; e++) {
                    unsigned b0 = e ? v4[ntp].z : v4[ntp].x;
                    unsigned b1 = e ? v4[ntp].w : v4[ntp].y;
                    mma8(o[ntp * 2 + e], a0, a1, a2, a3, b0, b1);
                }
            }
        }
        __syncthreads();

        if (kt + 2 <= kthi) {
            ISSUE_KV(kt + 2, p);
        } else {
            asm volatile("cp.async.commit_group;");
        }
    }

    // ---- epilogue: normalize, write in out-proj A-fragment layout ----
    float iA = 1.f / lA, iB = 1.f / lB;
    int qg = b * Sc + qt * 64 + wid * 16 + (lane >> 2);
#pragma unroll
    for (int nt = 0; nt < 8; nt++) {
#pragma unroll
        for (int j2 = 0; j2 < 2; j2++) {
            int col = h * 64 + nt * 8 + 2 * (lane & 3) + j2;
            storeAfrag(Operm, qg,     col, f2tf32(o[nt][j2] * iA));
            storeAfrag(Operm, qg + 8, col, f2tf32(o[nt][2 + j2] * iB));
        }
    }
#undef ISSUE_KV
}

// ---------------------------------------------------------------------------
extern "C" void kernel_launch(void* const* d_in, const int* in_sizes, int n_in,
                              void* d_out, int out_size)
{
    (void)in_sizes; (void)n_in; (void)out_size;
    const float* x     = (const float*)d_in[0];
    const float* in_w  = (const float*)d_in[1];
    const float* in_b  = (const float*)d_in[2];
    const float* out_w = (const float*)d_in[3];
    const float* out_b = (const float*)d_in[4];
    float* out = (float*)d_out;

    float* qkv;
    unsigned *xp, *ap, *wqp, *wop;
    cudaGetSymbolAddress((void**)&qkv, g_qkv);
    cudaGetSymbolAddress((void**)&xp,  g_xperm);
    cudaGetSymbolAddress((void**)&ap,  g_attnperm);
    cudaGetSymbolAddress((void**)&wqp, g_wqkvperm);
    cudaGetSymbolAddress((void**)&wop, g_woutperm);

    const int M = Bc * Sc;                      // 4096
    const int smem_gemm = GSTAGES * 32768;      // 96 KB
    const int smem_attn = 28672 * 4;            // 114688 B = 112 KB -> 2 CTAs/SM
    cudaFuncSetAttribute(gemm_tf32p,
                         cudaFuncAttributeMaxDynamicSharedMemorySize, smem_gemm);
    cudaFuncSetAttribute(attn_mma,
                         cudaFuncAttributeMaxDynamicSharedMemorySize, smem_attn);

    // Operand packers for projections
    permA<<<(M * Dc / 4 + 255) / 256, 256>>>(x, xp, M, Dc);
    permB<<<(3 * Dc * Dc / 4 + 255) / 256, 256>>>(in_w, wqp, 3 * Dc, Dc);
    permB<<<(Dc * Dc / 4 + 255) / 256, 256>>>(out_w, wop, Dc, Dc);

    // 1) QKV projection
    gemm_tf32p<<<dim3(3 * Dc / 128, M / 128), 256, smem_gemm>>>(
        xp, wqp, in_b, qkv, M, 3 * Dc, Dc);

    // 2) Pack attention fragments, run tensor-core attention
    frag_pack<<<dim3(Sc / 64, Hc, Bc), 256>>>(qkv);
    attn_mma<<<dim3(Sc / 64, Hc, Bc), 128, smem_attn>>>(ap);

    // 3) Output projection (consumes A-fragment layout written by attention)
    gemm_tf32p<<<dim3(Dc / 128, M / 128), 256, smem_gemm>>>(
        ap, wop, out_b, out, M, Dc, Dc);
}

// round 10
// speedup vs baseline: 3.9723x; 1.0219x over previous
#include <cuda_runtime.h>
#include <cstdint>

// Problem constants
#define Bc   2
#define Sc   2048
#define Dc   1024
#define Hc   16
#define HDc  64
#define Wc   128

// Scratch (allocation-free rule: __device__ globals)
__device__ unsigned g_xperm[Bc * Sc * Dc];      // x in A-fragment layout (tf32)
__device__ unsigned g_attnperm[Bc * Sc * Dc];   // attn out in A-fragment layout
__device__ unsigned g_wqkvperm[3 * Dc * Dc];    // in_proj_w in B-fragment layout
__device__ unsigned g_woutperm[Dc * Dc];        // out_proj_w in B-fragment layout
// Attention fragment buffers (per (b,h,tile64): 4096 words)
__device__ unsigned g_qfh[Bc * Sc * Dc];        // Q A-frag hi (scaled)
__device__ unsigned g_qfl[Bc * Sc * Dc];        // Q A-frag lo
__device__ unsigned g_kfh[Bc * Sc * Dc];        // K B-frag hi
__device__ unsigned g_kfl[Bc * Sc * Dc];        // K B-frag lo
__device__ unsigned g_vf [Bc * Sc * Dc];        // V^T B-frag (n=dim,k=key)

__device__ __forceinline__ unsigned f2tf32(float x) {
    unsigned r;
    asm("cvt.rna.tf32.f32 %0, %1;" : "=r"(r) : "f"(x));
    return r;
}

__device__ __forceinline__ void mma8(float* c, unsigned a0, unsigned a1,
                                     unsigned a2, unsigned a3,
                                     unsigned b0, unsigned b1) {
    asm volatile(
        "mma.sync.aligned.m16n8k8.row.col.f32.tf32.tf32.f32 "
        "{%0,%1,%2,%3}, {%4,%5,%6,%7}, {%8,%9}, {%0,%1,%2,%3};\n"
        : "+f"(c[0]), "+f"(c[1]), "+f"(c[2]), "+f"(c[3])
        : "r"(a0), "r"(a1), "r"(a2), "r"(a3), "r"(b0), "r"(b1));
}

// Swizzled P-staging address: 16x64 words, XOR kills the 8-way bank conflict.
#define SWP(r, c) ((r) * 64 + ((c) ^ (((r) & 3) << 3)))

// ---------------------------------------------------------------------------
// permA / permB: projection-GEMM operand packers (unchanged, proven)
// ---------------------------------------------------------------------------
__global__ __launch_bounds__(256) void permA(
    const float* __restrict__ X, unsigned* __restrict__ P, int M, int K)
{
    int idx = blockIdx.x * blockDim.x + threadIdx.x;
    int total = (M * K) >> 2;
    if (idx >= total) return;
    int nKB  = K >> 5;
    int lane = idx & 31;
    int mtg  = (idx >> 5) & 7;
    int kt   = (idx >> 8) & 3;
    int rest = idx >> 10;
    int kblk = rest % nKB;
    int mblk = rest / nKB;
    int r0 = mblk * 128 + mtg * 16 + (lane >> 2);
    int c0 = kblk * 32 + kt * 8 + (lane & 3);
    const float* x = X + (size_t)r0 * K + c0;
    uint4 v;
    v.x = f2tf32(x[0]);
    v.y = f2tf32(x[(size_t)8 * K]);
    v.z = f2tf32(x[4]);
    v.w = f2tf32(x[(size_t)8 * K + 4]);
    ((uint4*)P)[idx] = v;
}

__global__ __launch_bounds__(256) void permB(
    const float* __restrict__ X, unsigned* __restrict__ P, int N, int K)
{
    int idx = blockIdx.x * blockDim.x + threadIdx.x;
    int total = (N * K) >> 2;
    if (idx >= total) return;
    int nKB  = K >> 5;
    int lane = idx & 31;
    int ntp  = (idx >> 5) & 7;
    int kt   = (idx >> 8) & 3;
    int rest = idx >> 10;
    int kblk = rest % nKB;
    int nblk = rest / nKB;
    int n0 = nblk * 128 + ntp * 16 + (lane >> 2);
    int c0 = kblk * 32 + kt * 8 + (lane & 3);
    const float* x = X + (size_t)n0 * K + c0;
    uint4 v;
    v.x = f2tf32(x[0]);
    v.y = f2tf32(x[4]);
    v.z = f2tf32(x[(size_t)8 * K]);
    v.w = f2tf32(x[(size_t)8 * K + 4]);
    ((uint4*)P)[idx] = v;
}

// ---------------------------------------------------------------------------
// Shared GEMM mainloop body (128x128 tile, 3-stage cp.async, K-tile 32).
// ---------------------------------------------------------------------------
#define GSTAGES 3

#define GEMM_MAINLOOP(Ap_, Bp_, nKB_)                                          \
    float acc[4][4][4];                                                        \
    _Pragma("unroll")                                                          \
    for (int i = 0; i < 4; i++)                                                \
        _Pragma("unroll")                                                      \
        for (int j = 0; j < 4; j++)                                            \
            _Pragma("unroll")                                                  \
            for (int c = 0; c < 4; c++) acc[i][j][c] = 0.f;                    \
    const unsigned* Atile = (Ap_) + (size_t)blockIdx.y * (nKB_) * 4096;        \
    const unsigned* Btile = (Bp_) + (size_t)blockIdx.x * (nKB_) * 4096;        \
    const uint32_t sbase = (uint32_t)__cvta_generic_to_shared(smg);            \
    ISSUE_TILE(0);                                                             \
    ISSUE_TILE(1);                                                             \
    for (int t = 0; t < (nKB_); t++) {                                         \
        asm volatile("cp.async.wait_group 1;\n");                              \
        __syncthreads();                                                       \
        if (t + 2 < (nKB_)) { ISSUE_TILE(t + 2); }                             \
        else { asm volatile("cp.async.commit_group;\n"); }                     \
        const unsigned* sA = smg + (t % GSTAGES) * 8192;                       \
        const unsigned* sB = sA + 4096;                                        \
        _Pragma("unroll")                                                      \
        for (int kt = 0; kt < 4; kt++) {                                       \
            const int lx = lane << 2;                                          \
            uint4 af[4], bf[2];                                                \
            _Pragma("unroll")                                                  \
            for (int mt = 0; mt < 4; mt++)                                     \
                af[mt] = *(const uint4*)&sA[(kt * 8 + warp_m * 4 + mt) * 128 + lx]; \
            _Pragma("unroll")                                                  \
            for (int p = 0; p < 2; p++)                                        \
                bf[p] = *(const uint4*)&sB[(kt * 8 + warp_n * 2 + p) * 128 + lx]; \
            _Pragma("unroll")                                                  \
            for (int mt = 0; mt < 4; mt++) {                                   \
                _Pragma("unroll")                                              \
                for (int nt = 0; nt < 4; nt++) {                               \
                    const uint4& b4 = bf[nt >> 1];                             \
                    unsigned b0 = (nt & 1) ? b4.z : b4.x;                      \
                    unsigned b1 = (nt & 1) ? b4.w : b4.y;                      \
                    mma8(acc[mt][nt], af[mt].x, af[mt].y, af[mt].z, af[mt].w, b0, b1); \
                }                                                              \
            }                                                                  \
        }                                                                      \
    }

#define ISSUE_TILE(t)                                                          \
    {                                                                          \
        uint32_t st = sbase + ((t) % GSTAGES) * 32768u;                        \
        const unsigned* asrc = Atile + (size_t)(t) * 4096;                     \
        const unsigned* bsrc = Btile + (size_t)(t) * 4096;                     \
        _Pragma("unroll")                                                      \
        for (int j = 0; j < 4; j++) {                                          \
            int c = tid + 256 * j;                                             \
            asm volatile("cp.async.cg.shared.global [%0],[%1],16;\n"           \
                         :: "r"(st + c * 16u), "l"(asrc + c * 4));             \
            asm volatile("cp.async.cg.shared.global [%0],[%1],16;\n"           \
                         :: "r"(st + 16384u + c * 16u), "l"(bsrc + c * 4));    \
        }                                                                      \
        asm volatile("cp.async.commit_group;\n");                              \
    }

// ---------------------------------------------------------------------------
// Projection GEMM writing row-major C + bias (used for out-proj).
// ---------------------------------------------------------------------------
__global__ __launch_bounds__(256, 2) void gemm_tf32p(
    const unsigned* __restrict__ Ap, const unsigned* __restrict__ Bp,
    const float* __restrict__ bias, float* __restrict__ C,
    int M, int N, int K)
{
    extern __shared__ unsigned smg[];
    const int tid    = threadIdx.x;
    const int lane   = tid & 31;
    const int wid    = tid >> 5;
    const int warp_m = wid >> 2;
    const int warp_n = wid & 3;
    const int nKB    = K >> 5;

    GEMM_MAINLOOP(Ap, Bp, nKB)

    const int m0 = blockIdx.y * 128;
    const int n0 = blockIdx.x * 128;
#pragma unroll
    for (int mt = 0; mt < 4; mt++) {
        int row = m0 + warp_m * 64 + mt * 16 + (lane >> 2);
#pragma unroll
        for (int nt = 0; nt < 4; nt++) {
            int col = n0 + warp_n * 32 + nt * 8 + 2 * (lane & 3);
            float2 bv = *(const float2*)&bias[col];
            float2 o0 = make_float2(acc[mt][nt][0] + bv.x, acc[mt][nt][1] + bv.y);
            float2 o1 = make_float2(acc[mt][nt][2] + bv.x, acc[mt][nt][3] + bv.y);
            *(float2*)&C[(size_t)row * N + col]       = o0;
            *(float2*)&C[(size_t)(row + 8) * N + col] = o1;
        }
    }
}

// ---------------------------------------------------------------------------
// QKV GEMM with fused fragment-pack epilogue: writes Q(hi/lo,scaled),
// K(hi/lo), V^T fragments directly (no fp32 qkv round-trip, no frag_pack).
// Grid: x = 24 n-blocks (0-7 Q, 8-15 K, 16-23 V), y = 32 m-blocks.
// ---------------------------------------------------------------------------
__global__ __launch_bounds__(256, 2) void gemm_qkv(
    const unsigned* __restrict__ Ap, const unsigned* __restrict__ Bp,
    const float* __restrict__ bias)
{
    extern __shared__ unsigned smg[];
    const int tid    = threadIdx.x;
    const int lane   = tid & 31;
    const int wid    = tid >> 5;
    const int warp_m = wid >> 2;
    const int warp_n = wid & 3;
    const int nKB    = Dc >> 5;   // 32

    GEMM_MAINLOOP(Ap, Bp, nKB)

    const int m0 = blockIdx.y * 128;
    const int n0 = blockIdx.x * 128;
    const int kind = n0 >> 10;    // 0=Q, 1=K, 2=V

#pragma unroll
    for (int mt = 0; mt < 4; mt++) {
        int row = m0 + warp_m * 64 + mt * 16 + (lane >> 2);
#pragma unroll
        for (int nt = 0; nt < 4; nt++) {
            int col = n0 + warp_n * 32 + nt * 8 + 2 * (lane & 3);
            float2 bv = *(const float2*)&bias[col];
            float v4[4] = {acc[mt][nt][0] + bv.x, acc[mt][nt][1] + bv.y,
                           acc[mt][nt][2] + bv.x, acc[mt][nt][3] + bv.y};
#pragma unroll
            for (int e = 0; e < 4; e++) {
                int r = row + (e >> 1) * 8;
                int c = col + (e & 1);
                int s = r & (Sc - 1), b = r >> 11;
                int cc = c & 1023;
                int h = cc >> 6, d = cc & 63;
                size_t base = ((size_t)(b * Hc + h) * 32 + (s >> 6)) * 4096;
                if (kind == 0) {
                    float q = v4[e] * 0.125f;
                    unsigned hi = f2tf32(q);
                    unsigned lo = f2tf32(q - __uint_as_float(hi));
                    int idx = ((d >> 3) * 128 + ((s >> 4) & 3) * 32 + (s & 7) * 4 + (d & 3)) * 4
                              + ((s >> 3) & 1) + 2 * ((d >> 2) & 1);
                    g_qfh[base + idx] = hi;
                    g_qfl[base + idx] = lo;
                } else if (kind == 1) {
                    unsigned hi = f2tf32(v4[e]);
                    unsigned lo = f2tf32(v4[e] - __uint_as_float(hi));
                    int idx = ((d >> 3) * 128 + ((s >> 4) & 3) * 32 + (s & 7) * 4 + (d & 3)) * 4
                              + ((d >> 2) & 1) + 2 * ((s >> 3) & 1);
                    g_kfh[base + idx] = hi;
                    g_kfl[base + idx] = lo;
                } else {
                    int k6 = s & 63;
                    int idx = ((k6 >> 3) * 128 + (d >> 4) * 32 + (d & 7) * 4 + (k6 & 3)) * 4
                              + ((k6 >> 2) & 1) + 2 * ((d >> 3) & 1);
                    g_vf[base + idx] = f2tf32(v4[e]);
                }
            }
        }
    }
}

// ---------------------------------------------------------------------------
// Tensor-core windowed attention (unchanged from R8).
// ---------------------------------------------------------------------------
__device__ __forceinline__ void storeAfrag(unsigned* P, int q, int col, unsigned v) {
    int mblk = q >> 7, mtg = (q >> 4) & 7, rr = q & 15;
    int kblk = col >> 5, kt = (col >> 3) & 3;
    int lanep = (rr & 7) * 4 + (col & 3);
    int slot  = (rr >> 3) + 2 * ((col >> 2) & 1);
    P[(size_t)(mblk * 32 + kblk) * 4096 + kt * 1024 + mtg * 128 + lanep * 4 + slot] = v;
}

__global__ __launch_bounds__(128, 2) void attn_mma(unsigned* __restrict__ Operm)
{
    extern __shared__ unsigned sm[];
    const int tid = threadIdx.x, lane = tid & 31, wid = tid >> 5;
    const int qt = blockIdx.x, h = blockIdx.y, b = blockIdx.z;
    const int bh = b * Hc + h;
    const uint32_t sbase = (uint32_t)__cvta_generic_to_shared(sm);

    {
        const unsigned* qh_ = g_qfh + ((size_t)bh * 32 + qt) * 4096;
        const unsigned* ql_ = g_qfl + ((size_t)bh * 32 + qt) * 4096;
#pragma unroll
        for (int j = 0; j < 8; j++) {
            int c = tid + 128 * j;
            asm volatile("cp.async.cg.shared.global [%0],[%1],16;"
                         :: "r"(sbase + c * 16u), "l"(qh_ + c * 4));
            asm volatile("cp.async.cg.shared.global [%0],[%1],16;"
                         :: "r"(sbase + 16384u + c * 16u), "l"(ql_ + c * 4));
        }
        asm volatile("cp.async.commit_group;");
        asm volatile("cp.async.wait_group 0;");
    }
    __syncthreads();
    uint4 qh[8], ql[8];
#pragma unroll
    for (int kd = 0; kd < 8; kd++) {
        qh[kd] = *(const uint4*)&sm[(kd * 4 + wid) * 128 + lane * 4];
        ql[kd] = *(const uint4*)&sm[4096 + (kd * 4 + wid) * 128 + lane * 4];
    }
    __syncthreads();

    const int ktlo = (qt - 2 > 0) ? qt - 2 : 0;
    const int kthi = (qt + 2 < 31) ? qt + 2 : 31;
    const int nT = kthi - ktlo + 1;

#define ISSUE_KV(kt, p)                                                         \
    {                                                                           \
        const unsigned* kh_ = g_kfh + ((size_t)bh * 32 + (kt)) * 4096;          \
        const unsigned* kl_ = g_kfl + ((size_t)bh * 32 + (kt)) * 4096;          \
        const unsigned* v_  = g_vf  + ((size_t)bh * 32 + (kt)) * 4096;          \
        uint32_t dst = sbase + (p) * 49152u;                                    \
        _Pragma("unroll")                                                       \
        for (int j = 0; j < 8; j++) {                                           \
            int c = tid + 128 * j;                                              \
            asm volatile("cp.async.cg.shared.global [%0],[%1],16;"              \
                         :: "r"(dst + c * 16u), "l"(kh_ + c * 4));              \
            asm volatile("cp.async.cg.shared.global [%0],[%1],16;"              \
                         :: "r"(dst + 16384u + c * 16u), "l"(kl_ + c * 4));     \
            asm volatile("cp.async.cg.shared.global [%0],[%1],16;"              \
                         :: "r"(dst + 32768u + c * 16u), "l"(v_ + c * 4));      \
        }                                                                       \
        asm volatile("cp.async.commit_group;");                                 \
    }

    ISSUE_KV(ktlo, 0);
    ISSUE_KV(ktlo + 1, 1);

    float o[8][4];
#pragma unroll
    for (int i = 0; i < 8; i++)
#pragma unroll
        for (int c = 0; c < 4; c++) o[i][c] = 0.f;
    float mA = -1e30f, mB = -1e30f, lA = 0.f, lB = 0.f;

    unsigned* sP = sm + 24576 + wid * 1024;

    for (int j = 0; j < nT; j++) {
        const int kt = ktlo + j, p = j & 1;
        asm volatile("cp.async.wait_group 1;");
        __syncthreads();

        const unsigned* bKh = sm + p * 12288;
        const unsigned* bKl = bKh + 4096;
        const unsigned* bV  = bKh + 8192;

        float s[8][4];
#pragma unroll
        for (int i = 0; i < 8; i++)
#pragma unroll
            for (int c = 0; c < 4; c++) s[i][c] = 0.f;

#pragma unroll
        for (int kd = 0; kd < 8; kd++) {
            uint4 kh4[4], kl4[4];
#pragma unroll
            for (int ntp = 0; ntp < 4; ntp++) {
                kh4[ntp] = *(const uint4*)&bKh[(kd * 4 + ntp) * 128 + lane * 4];
                kl4[ntp] = *(const uint4*)&bKl[(kd * 4 + ntp) * 128 + lane * 4];
            }
#pragma unroll
            for (int ntp = 0; ntp < 4; ntp++) {
#pragma unroll
                for (int e = 0; e < 2; e++) {
                    unsigned bh0 = e ? kh4[ntp].z : kh4[ntp].x;
                    unsigned bh1 = e ? kh4[ntp].w : kh4[ntp].y;
                    unsigned bl0 = e ? kl4[ntp].z : kl4[ntp].x;
                    unsigned bl1 = e ? kl4[ntp].w : kl4[ntp].y;
                    float* c = s[ntp * 2 + e];
                    mma8(c, qh[kd].x, qh[kd].y, qh[kd].z, qh[kd].w, bh0, bh1);
                    mma8(c, ql[kd].x, ql[kd].y, ql[kd].z, ql[kd].w, bh0, bh1);
                    mma8(c, qh[kd].x, qh[kd].y, qh[kd].z, qh[kd].w, bl0, bl1);
                }
            }
        }

        if (kt - qt == 2 || qt - kt == 2) {
            int q1 = qt * 64 + wid * 16 + (lane >> 2);
            int k00 = kt * 64 + 2 * (lane & 3);
#pragma unroll
            for (int nt = 0; nt < 8; nt++) {
#pragma unroll
                for (int ci = 0; ci < 4; ci++) {
                    int qv = q1 + ((ci >= 2) ? 8 : 0);
                    int kv = k00 + nt * 8 + (ci & 1);
                    int d = qv - kv; d = (d < 0) ? -d : d;
                    if (d > Wc) s[nt][ci] = -1e30f;
                }
            }
        }

        float tA = -1e30f, tB = -1e30f;
#pragma unroll
        for (int nt = 0; nt < 8; nt++) {
            tA = fmaxf(tA, fmaxf(s[nt][0], s[nt][1]));
            tB = fmaxf(tB, fmaxf(s[nt][2], s[nt][3]));
        }
        tA = fmaxf(tA, __shfl_xor_sync(0xffffffffu, tA, 1));
        tA = fmaxf(tA, __shfl_xor_sync(0xffffffffu, tA, 2));
        tB = fmaxf(tB, __shfl_xor_sync(0xffffffffu, tB, 1));
        tB = fmaxf(tB, __shfl_xor_sync(0xffffffffu, tB, 2));
        float mnA = fmaxf(mA, tA), mnB = fmaxf(mB, tB);
        float aA = __expf(mA - mnA), aB = __expf(mB - mnB);
        mA = mnA; mB = mnB;
        float sumA = 0.f, sumB = 0.f;
#pragma unroll
        for (int nt = 0; nt < 8; nt++) {
            s[nt][0] = __expf(s[nt][0] - mnA);
            s[nt][1] = __expf(s[nt][1] - mnA);
            s[nt][2] = __expf(s[nt][2] - mnB);
            s[nt][3] = __expf(s[nt][3] - mnB);
            sumA += s[nt][0] + s[nt][1];
            sumB += s[nt][2] + s[nt][3];
        }
        sumA += __shfl_xor_sync(0xffffffffu, sumA, 1);
        sumA += __shfl_xor_sync(0xffffffffu, sumA, 2);
        sumB += __shfl_xor_sync(0xffffffffu, sumB, 1);
        sumB += __shfl_xor_sync(0xffffffffu, sumB, 2);
        lA = lA * aA + sumA;
        lB = lB * aB + sumB;
#pragma unroll
        for (int nt = 0; nt < 8; nt++) {
            o[nt][0] *= aA; o[nt][1] *= aA;
            o[nt][2] *= aB; o[nt][3] *= aB;
        }

        {
            int rA = lane >> 2, cb = 2 * (lane & 3);
#pragma unroll
            for (int nt = 0; nt < 8; nt++) {
                int c = nt * 8 + cb;
                uint2 v0 = make_uint2(f2tf32(s[nt][0]), f2tf32(s[nt][1]));
                uint2 v1 = make_uint2(f2tf32(s[nt][2]), f2tf32(s[nt][3]));
                *(uint2*)&sP[SWP(rA, c)]     = v0;
                *(uint2*)&sP[SWP(rA + 8, c)] = v1;
            }
        }
        __syncwarp();

#pragma unroll
        for (int kk = 0; kk < 8; kk++) {
            int rA = lane >> 2, cA = kk * 8 + (lane & 3);
            unsigned a0 = sP[SWP(rA, cA)];
            unsigned a1 = sP[SWP(rA + 8, cA)];
            unsigned a2 = sP[SWP(rA, cA + 4)];
            unsigned a3 = sP[SWP(rA + 8, cA + 4)];
            uint4 v4[4];
#pragma unroll
            for (int ntp = 0; ntp < 4; ntp++)
                v4[ntp] = *(const uint4*)&bV[(kk * 4 + ntp) * 128 + lane * 4];
#pragma unroll
            for (int ntp = 0; ntp < 4; ntp++) {
#pragma unroll
                for (int e = 0; e < 2; e++) {
                    unsigned b0 = e ? v4[ntp].z : v4[ntp].x;
                    unsigned b1 = e ? v4[ntp].w : v4[ntp].y;
                    mma8(o[ntp * 2 + e], a0, a1, a2, a3, b0, b1);
                }
            }
        }
        __syncthreads();

        if (kt + 2 <= kthi) {
            ISSUE_KV(kt + 2, p);
        } else {
            asm volatile("cp.async.commit_group;");
        }
    }

    float iA = 1.f / lA, iB = 1.f / lB;
    int qg = b * Sc + qt * 64 + wid * 16 + (lane >> 2);
#pragma unroll
    for (int nt = 0; nt < 8; nt++) {
#pragma unroll
        for (int j2 = 0; j2 < 2; j2++) {
            int col = h * 64 + nt * 8 + 2 * (lane & 3) + j2;
            storeAfrag(Operm, qg,     col, f2tf32(o[nt][j2] * iA));
            storeAfrag(Operm, qg + 8, col, f2tf32(o[nt][2 + j2] * iB));
        }
    }
#undef ISSUE_KV
}

// ---------------------------------------------------------------------------
extern "C" void kernel_launch(void* const* d_in, const int* in_sizes, int n_in,
                              void* d_out, int out_size)
{
    (void)in_sizes; (void)n_in; (void)out_size;
    const float* x     = (const float*)d_in[0];
    const float* in_w  = (const float*)d_in[1];
    const float* in_b  = (const float*)d_in[2];
    const float* out_w = (const float*)d_in[3];
    const float* out_b = (const float*)d_in[4];
    float* out = (float*)d_out;

    unsigned *xp, *ap, *wqp, *wop;
    cudaGetSymbolAddress((void**)&xp,  g_xperm);
    cudaGetSymbolAddress((void**)&ap,  g_attnperm);
    cudaGetSymbolAddress((void**)&wqp, g_wqkvperm);
    cudaGetSymbolAddress((void**)&wop, g_woutperm);

    const int M = Bc * Sc;                      // 4096
    const int smem_gemm = GSTAGES * 32768;      // 96 KB
    const int smem_attn = 28672 * 4;            // 114688 B = 112 KB -> 2 CTAs/SM
    cudaFuncSetAttribute(gemm_tf32p,
                         cudaFuncAttributeMaxDynamicSharedMemorySize, smem_gemm);
    cudaFuncSetAttribute(gemm_qkv,
                         cudaFuncAttributeMaxDynamicSharedMemorySize, smem_gemm);
    cudaFuncSetAttribute(attn_mma,
                         cudaFuncAttributeMaxDynamicSharedMemorySize, smem_attn);

    // Operand packers for projections
    permA<<<(M * Dc / 4 + 255) / 256, 256>>>(x, xp, M, Dc);
    permB<<<(3 * Dc * Dc / 4 + 255) / 256, 256>>>(in_w, wqp, 3 * Dc, Dc);
    permB<<<(Dc * Dc / 4 + 255) / 256, 256>>>(out_w, wop, Dc, Dc);

    // 1) QKV projection with fused Q/K/V fragment-pack epilogue
    gemm_qkv<<<dim3(3 * Dc / 128, M / 128), 256, smem_gemm>>>(xp, wqp, in_b);

    // 2) Tensor-core attention (writes out-proj A-fragments directly)
    attn_mma<<<dim3(Sc / 64, Hc, Bc), 128, smem_attn>>>(ap);

    // 3) Output projection
    gemm_tf32p<<<dim3(Dc / 128, M / 128), 256, smem_gemm>>>(
        ap, wop, out_b, out, M, Dc, Dc);
}

// round 13
// speedup vs baseline: 6.9760x; 1.7561x over previous
#include <cuda_runtime.h>
#include <cuda_fp16.h>
#include <cstdint>

// Problem constants
#define Bc   2
#define Sc   2048
#define Dc   1024
#define Hc   16
#define HDc  64
#define Wc   128

// Scratch (allocation-free rule: __device__ globals). All fp16 fragments,
// stored as u32 words (2 halves each).
__device__ unsigned g_xperm[Bc * Sc * Dc / 2];     // x, A-frag layout
__device__ unsigned g_attnperm[Bc * Sc * Dc / 2];  // attn out, A-frag layout
__device__ unsigned g_wqkvperm[3 * Dc * Dc / 2];   // in_proj_w, B-frag layout
__device__ unsigned g_woutperm[Dc * Dc / 2];       // out_proj_w, B-frag layout
// Attention fragment buffers: per (b,h,tile64) block = 2048 words (8KB)
__device__ unsigned g_qfh[Bc * Hc * 32 * 2048];    // Q A-frag hi (scaled)
__device__ unsigned g_qfl[Bc * Hc * 32 * 2048];    // Q A-frag lo
__device__ unsigned g_kfh[Bc * Hc * 32 * 2048];    // K B-frag hi
__device__ unsigned g_kfl[Bc * Hc * 32 * 2048];    // K B-frag lo
__device__ unsigned g_vf [Bc * Hc * 32 * 2048];    // V^T B-frag (n=dim,k=key)

__device__ __forceinline__ unsigned h2(float a, float b) {
    __half2 t = __floats2half2_rn(a, b);
    return *reinterpret_cast<unsigned*>(&t);
}
__device__ __forceinline__ float hi16(float x) {
    return __half2float(__float2half_rn(x));
}

__device__ __forceinline__ void mma16(float* c, unsigned a0, unsigned a1,
                                      unsigned a2, unsigned a3,
                                      unsigned b0, unsigned b1) {
    asm volatile(
        "mma.sync.aligned.m16n8k16.row.col.f32.f16.f16.f32 "
        "{%0,%1,%2,%3}, {%4,%5,%6,%7}, {%8,%9}, {%0,%1,%2,%3};\n"
        : "+f"(c[0]), "+f"(c[1]), "+f"(c[2]), "+f"(c[3])
        : "r"(a0), "r"(a1), "r"(a2), "r"(a3), "r"(b0), "r"(b1));
}

// ---------------------------------------------------------------------------
// fp16 operand packers. Word layout per (blk128, kblk32) block of 2048 words:
//   idx = kstep*1024 + grp*128 + lane*4 + slot
// A: slot = rowbit | kbbit<<1; row = grp*16 + rowbit*8 + lane/4,
//    k = kstep*16 + kbbit*8 + 2*(lane%4) + {0,1}  (2 halves per word)
// B: slot = e<<1 | kb;  n = grp*16 + e*8 + lane/4,
//    k = kstep*16 + kb*8 + 2*(lane%4) + {0,1}
// ---------------------------------------------------------------------------
__global__ __launch_bounds__(256) void permA_h(
    const float* __restrict__ X, unsigned* __restrict__ P, int M, int K)
{
    int idx = blockIdx.x * 256 + threadIdx.x;
    if (idx >= (M * K) >> 1) return;
    int slot = idx & 3;
    int lane = (idx >> 2) & 31;
    int mtg  = (idx >> 7) & 7;
    int kstep = (idx >> 10) & 1;
    int rest = idx >> 11;
    int nKB = K >> 5;
    int kblk = rest % nKB, mblk = rest / nKB;
    int r = mblk * 128 + mtg * 16 + (slot & 1) * 8 + (lane >> 2);
    int d = kblk * 32 + kstep * 16 + ((slot >> 1) & 1) * 8 + 2 * (lane & 3);
    const float* x = X + (size_t)r * K + d;
    P[idx] = h2(x[0], x[1]);
}

__global__ __launch_bounds__(256) void permB_h(
    const float* __restrict__ X, unsigned* __restrict__ P, int N, int K)
{
    int idx = blockIdx.x * 256 + threadIdx.x;
    if (idx >= (N * K) >> 1) return;
    int slot = idx & 3;
    int lane = (idx >> 2) & 31;
    int ntp  = (idx >> 7) & 7;
    int kstep = (idx >> 10) & 1;
    int rest = idx >> 11;
    int nKB = K >> 5;
    int kblk = rest % nKB, nblk = rest / nKB;
    int e = (slot >> 1) & 1, kb = slot & 1;
    int n = nblk * 128 + ntp * 16 + e * 8 + (lane >> 2);
    int d = kblk * 32 + kstep * 16 + kb * 8 + 2 * (lane & 3);
    const float* x = X + (size_t)n * K + d;
    P[idx] = h2(x[0], x[1]);
}

// ---------------------------------------------------------------------------
// Shared fp16 GEMM mainloop (128x128 tile, K-tile 32, 3-stage cp.async).
// Stage = A 2048 words + B 2048 words = 16KB.
// ---------------------------------------------------------------------------
#define GSTAGES 3

#define ISSUE_TILE(t)                                                          \
    {                                                                          \
        uint32_t st = sbase + ((t) % GSTAGES) * 16384u;                        \
        const unsigned* asrc = Atile + (size_t)(t) * 2048;                     \
        const unsigned* bsrc = Btile + (size_t)(t) * 2048;                     \
        _Pragma("unroll")                                                      \
        for (int j = 0; j < 2; j++) {                                          \
            int c = tid + 256 * j;                                             \
            asm volatile("cp.async.cg.shared.global [%0],[%1],16;\n"           \
                         :: "r"(st + c * 16u), "l"(asrc + c * 4));             \
            asm volatile("cp.async.cg.shared.global [%0],[%1],16;\n"           \
                         :: "r"(st + 8192u + c * 16u), "l"(bsrc + c * 4));     \
        }                                                                      \
        asm volatile("cp.async.commit_group;\n");                              \
    }

#define GEMM_MAINLOOP(Ap_, Bp_, nKB_)                                          \
    float acc[4][4][4];                                                        \
    _Pragma("unroll")                                                          \
    for (int i = 0; i < 4; i++)                                                \
        _Pragma("unroll")                                                      \
        for (int j = 0; j < 4; j++)                                            \
            _Pragma("unroll")                                                  \
            for (int c = 0; c < 4; c++) acc[i][j][c] = 0.f;                    \
    const unsigned* Atile = (Ap_) + (size_t)blockIdx.y * (nKB_) * 2048;        \
    const unsigned* Btile = (Bp_) + (size_t)blockIdx.x * (nKB_) * 2048;        \
    const uint32_t sbase = (uint32_t)__cvta_generic_to_shared(smg);            \
    ISSUE_TILE(0);                                                             \
    ISSUE_TILE(1);                                                             \
    for (int t = 0; t < (nKB_); t++) {                                         \
        asm volatile("cp.async.wait_group 1;\n");                              \
        __syncthreads();                                                       \
        if (t + 2 < (nKB_)) { ISSUE_TILE(t + 2); }                             \
        else { asm volatile("cp.async.commit_group;\n"); }                     \
        const unsigned* sA = smg + (t % GSTAGES) * 4096;                       \
        const unsigned* sB = sA + 2048;                                        \
        _Pragma("unroll")                                                      \
        for (int ks = 0; ks < 2; ks++) {                                       \
            const int lx = lane << 2;                                          \
            uint4 af[4], bf[2];                                                \
            _Pragma("unroll")                                                  \
            for (int mt = 0; mt < 4; mt++)                                     \
                af[mt] = *(const uint4*)&sA[ks * 1024 + (warp_m * 4 + mt) * 128 + lx]; \
            _Pragma("unroll")                                                  \
            for (int p = 0; p < 2; p++)                                        \
                bf[p] = *(const uint4*)&sB[ks * 1024 + (warp_n * 2 + p) * 128 + lx]; \
            _Pragma("unroll")                                                  \
            for (int mt = 0; mt < 4; mt++) {                                   \
                _Pragma("unroll")                                              \
                for (int nt = 0; nt < 4; nt++) {                               \
                    const uint4& b4 = bf[nt >> 1];                             \
                    unsigned b0 = (nt & 1) ? b4.z : b4.x;                      \
                    unsigned b1 = (nt & 1) ? b4.w : b4.y;                      \
                    mma16(acc[mt][nt], af[mt].x, af[mt].y, af[mt].z, af[mt].w, b0, b1); \
                }                                                              \
            }                                                                  \
        }                                                                      \
    }

// ---------------------------------------------------------------------------
// Out-projection GEMM: row-major fp32 C + bias.
// ---------------------------------------------------------------------------
__global__ __launch_bounds__(256, 2) void gemm_h(
    const unsigned* __restrict__ Ap, const unsigned* __restrict__ Bp,
    const float* __restrict__ bias, float* __restrict__ C,
    int M, int N, int K)
{
    extern __shared__ unsigned smg[];
    const int tid    = threadIdx.x;
    const int lane   = tid & 31;
    const int wid    = tid >> 5;
    const int warp_m = wid >> 2;
    const int warp_n = wid & 3;
    const int nKB    = K >> 5;

    GEMM_MAINLOOP(Ap, Bp, nKB)

    const int m0 = blockIdx.y * 128;
    const int n0 = blockIdx.x * 128;
#pragma unroll
    for (int mt = 0; mt < 4; mt++) {
        int row = m0 + warp_m * 64 + mt * 16 + (lane >> 2);
#pragma unroll
        for (int nt = 0; nt < 4; nt++) {
            int col = n0 + warp_n * 32 + nt * 8 + 2 * (lane & 3);
            float2 bv = *(const float2*)&bias[col];
            float2 o0 = make_float2(acc[mt][nt][0] + bv.x, acc[mt][nt][1] + bv.y);
            float2 o1 = make_float2(acc[mt][nt][2] + bv.x, acc[mt][nt][3] + bv.y);
            *(float2*)&C[(size_t)row * N + col]       = o0;
            *(float2*)&C[(size_t)(row + 8) * N + col] = o1;
        }
    }
}

// ---------------------------------------------------------------------------
// QKV GEMM with fused fp16 fragment-pack epilogue.
// Grid.x: 0-7 Q, 8-15 K, 16-23 V (128-col bands).
// ---------------------------------------------------------------------------
__global__ __launch_bounds__(256, 2) void gemm_qkv(
    const unsigned* __restrict__ Ap, const unsigned* __restrict__ Bp,
    const float* __restrict__ bias)
{
    extern __shared__ unsigned smg[];
    const int tid    = threadIdx.x;
    const int lane   = tid & 31;
    const int wid    = tid >> 5;
    const int warp_m = wid >> 2;
    const int warp_n = wid & 3;
    const int nKB    = Dc >> 5;

    GEMM_MAINLOOP(Ap, Bp, nKB)

    const int m0 = blockIdx.y * 128;
    const int n0 = blockIdx.x * 128;
    const int kind = n0 >> 10;    // 0=Q, 1=K, 2=V
    __half* gv = (__half*)g_vf;

#pragma unroll
    for (int mt = 0; mt < 4; mt++) {
        int row = m0 + warp_m * 64 + mt * 16 + (lane >> 2);
#pragma unroll
        for (int nt = 0; nt < 4; nt++) {
            int col = n0 + warp_n * 32 + nt * 8 + 2 * (lane & 3);
            float2 bv = *(const float2*)&bias[col];
            float v0 = acc[mt][nt][0] + bv.x, v1 = acc[mt][nt][1] + bv.y;
            float v2 = acc[mt][nt][2] + bv.x, v3 = acc[mt][nt][3] + bv.y;

            int s = row & (Sc - 1), b = row >> 11;
            int cc = col & 1023;
            int h = cc >> 6, d = cc & 63;           // d even
            int sl = s & 63;
            size_t base = ((size_t)(b * Hc + h) * 32 + (s >> 6)) * 2048;

            if (kind == 0) {
                float q0 = v0 * 0.125f, q1 = v1 * 0.125f;
                float q2 = v2 * 0.125f, q3 = v3 * 0.125f;
                int idx = (d >> 4) * 512 + ((sl >> 4) & 3) * 128
                        + (((sl & 7) << 2) | ((d >> 1) & 3)) * 4
                        + (((d >> 3) & 1) << 1);
                g_qfh[base + idx]     = h2(q0, q1);
                g_qfh[base + idx + 1] = h2(q2, q3);
                g_qfl[base + idx]     = h2(q0 - hi16(q0), q1 - hi16(q1));
                g_qfl[base + idx + 1] = h2(q2 - hi16(q2), q3 - hi16(q3));
            } else if (kind == 1) {
                int idx = (d >> 4) * 512 + ((sl >> 4) & 3) * 128
                        + (((sl & 7) << 2) | ((d >> 1) & 3)) * 4
                        + ((d >> 3) & 1);
                g_kfh[base + idx]     = h2(v0, v1);       // e=0 (row s)
                g_kfh[base + idx + 2] = h2(v2, v3);       // e=1 (row s+8)
                g_kfl[base + idx]     = h2(v0 - hi16(v0), v1 - hi16(v1));
                g_kfl[base + idx + 2] = h2(v2 - hi16(v2), v3 - hi16(v3));
            } else {
                float vv[4] = {v0, v1, v2, v3};
#pragma unroll
                for (int e = 0; e < 4; e++) {
                    int key = sl + (e >> 1) * 8;
                    int dim = d + (e & 1);
                    int widx = (key >> 4) * 512 + ((dim >> 4) & 3) * 128
                             + (((dim & 7) << 2) | ((key >> 1) & 3)) * 4
                             + ((((dim >> 3) & 1) << 1) | ((key >> 3) & 1));
                    gv[(base + widx) * 2 + (key & 1)] = __float2half_rn(vv[e]);
                }
            }
        }
    }
}

// ---------------------------------------------------------------------------
// fp16 tensor-core windowed attention. Block = (b,h,qtile64), 4 warps.
// S via 3-leg fp16 hi/lo; P feeds PV directly from registers (C layout ==
// A-frag layout for m16n8k16). Smem 48KB -> 3 CTAs/SM.
// ---------------------------------------------------------------------------
__global__ __launch_bounds__(128, 3) void attn_mma(unsigned* __restrict__ Operm)
{
    extern __shared__ unsigned sm[];
    // buf p @ p*6144 words: Kh 2048 | Kl 2048 | V 2048
    const int tid = threadIdx.x, lane = tid & 31, wid = tid >> 5;
    const int qt = blockIdx.x, h = blockIdx.y, b = blockIdx.z;
    const int bh = b * Hc + h;
    const uint32_t sbase = (uint32_t)__cvta_generic_to_shared(sm);

    // --- Q staging into buf0 area, then to regs ---
    {
        const unsigned* qh_ = g_qfh + ((size_t)bh * 32 + qt) * 2048;
        const unsigned* ql_ = g_qfl + ((size_t)bh * 32 + qt) * 2048;
#pragma unroll
        for (int j = 0; j < 4; j++) {
            int c = tid + 128 * j;
            asm volatile("cp.async.cg.shared.global [%0],[%1],16;"
                         :: "r"(sbase + c * 16u), "l"(qh_ + c * 4));
            asm volatile("cp.async.cg.shared.global [%0],[%1],16;"
                         :: "r"(sbase + 8192u + c * 16u), "l"(ql_ + c * 4));
        }
        asm volatile("cp.async.commit_group;");
        asm volatile("cp.async.wait_group 0;");
    }
    __syncthreads();
    uint4 qh[4], ql[4];
#pragma unroll
    for (int ks = 0; ks < 4; ks++) {
        qh[ks] = *(const uint4*)&sm[ks * 512 + wid * 128 + lane * 4];
        ql[ks] = *(const uint4*)&sm[2048 + ks * 512 + wid * 128 + lane * 4];
    }
    __syncthreads();

    const int ktlo = (qt - 2 > 0) ? qt - 2 : 0;
    const int kthi = (qt + 2 < 31) ? qt + 2 : 31;
    const int nT = kthi - ktlo + 1;

#define ISSUE_KV(kt, p)                                                         \
    {                                                                           \
        const unsigned* kh_ = g_kfh + ((size_t)bh * 32 + (kt)) * 2048;          \
        const unsigned* kl_ = g_kfl + ((size_t)bh * 32 + (kt)) * 2048;          \
        const unsigned* v_  = g_vf  + ((size_t)bh * 32 + (kt)) * 2048;          \
        uint32_t dst = sbase + (p) * 24576u;                                    \
        _Pragma("unroll")                                                       \
        for (int j = 0; j < 4; j++) {                                           \
            int c = tid + 128 * j;                                              \
            asm volatile("cp.async.cg.shared.global [%0],[%1],16;"              \
                         :: "r"(dst + c * 16u), "l"(kh_ + c * 4));              \
            asm volatile("cp.async.cg.shared.global [%0],[%1],16;"              \
                         :: "r"(dst + 8192u + c * 16u), "l"(kl_ + c * 4));      \
            asm volatile("cp.async.cg.shared.global [%0],[%1],16;"              \
                         :: "r"(dst + 16384u + c * 16u), "l"(v_ + c * 4));      \
        }                                                                       \
        asm volatile("cp.async.commit_group;");                                 \
    }

    ISSUE_KV(ktlo, 0);
    ISSUE_KV(ktlo + 1, 1);

    float o[8][4];
#pragma unroll
    for (int i = 0; i < 8; i++)
#pragma unroll
        for (int c = 0; c < 4; c++) o[i][c] = 0.f;
    float mA = -1e30f, mB = -1e30f, lA = 0.f, lB = 0.f;

    for (int j = 0; j < nT; j++) {
        const int kt = ktlo + j, p = j & 1;
        asm volatile("cp.async.wait_group 1;");
        __syncthreads();

        const unsigned* bKh = sm + p * 6144;
        const unsigned* bKl = bKh + 2048;
        const unsigned* bV  = bKh + 4096;

        // ---- S = Q K^T (3-leg fp16 hi/lo) ----
        float s[8][4];
#pragma unroll
        for (int i = 0; i < 8; i++)
#pragma unroll
            for (int c = 0; c < 4; c++) s[i][c] = 0.f;

#pragma unroll
        for (int ks = 0; ks < 4; ks++) {
            uint4 kh4[4], kl4[4];
#pragma unroll
            for (int ntp = 0; ntp < 4; ntp++) {
                kh4[ntp] = *(const uint4*)&bKh[ks * 512 + ntp * 128 + lane * 4];
                kl4[ntp] = *(const uint4*)&bKl[ks * 512 + ntp * 128 + lane * 4];
            }
#pragma unroll
            for (int ntp = 0; ntp < 4; ntp++) {
#pragma unroll
                for (int e = 0; e < 2; e++) {
                    unsigned bh0 = e ? kh4[ntp].z : kh4[ntp].x;
                    unsigned bh1 = e ? kh4[ntp].w : kh4[ntp].y;
                    unsigned bl0 = e ? kl4[ntp].z : kl4[ntp].x;
                    unsigned bl1 = e ? kl4[ntp].w : kl4[ntp].y;
                    float* c = s[ntp * 2 + e];
                    mma16(c, qh[ks].x, qh[ks].y, qh[ks].z, qh[ks].w, bh0, bh1);
                    mma16(c, ql[ks].x, ql[ks].y, ql[ks].z, ql[ks].w, bh0, bh1);
                    mma16(c, qh[ks].x, qh[ks].y, qh[ks].z, qh[ks].w, bl0, bl1);
                }
            }
        }

        // ---- banded mask (only outermost tiles are partial) ----
        if (kt - qt == 2 || qt - kt == 2) {
            int q1 = qt * 64 + wid * 16 + (lane >> 2);
            int k00 = kt * 64 + 2 * (lane & 3);
#pragma unroll
            for (int nt = 0; nt < 8; nt++) {
#pragma unroll
                for (int ci = 0; ci < 4; ci++) {
                    int qv = q1 + ((ci >= 2) ? 8 : 0);
                    int kv = k00 + nt * 8 + (ci & 1);
                    int d = qv - kv; d = (d < 0) ? -d : d;
                    if (d > Wc) s[nt][ci] = -1e30f;
                }
            }
        }

        // ---- online softmax ----
        float tA = -1e30f, tB = -1e30f;
#pragma unroll
        for (int nt = 0; nt < 8; nt++) {
            tA = fmaxf(tA, fmaxf(s[nt][0], s[nt][1]));
            tB = fmaxf(tB, fmaxf(s[nt][2], s[nt][3]));
        }
        tA = fmaxf(tA, __shfl_xor_sync(0xffffffffu, tA, 1));
        tA = fmaxf(tA, __shfl_xor_sync(0xffffffffu, tA, 2));
        tB = fmaxf(tB, __shfl_xor_sync(0xffffffffu, tB, 1));
        tB = fmaxf(tB, __shfl_xor_sync(0xffffffffu, tB, 2));
        float mnA = fmaxf(mA, tA), mnB = fmaxf(mB, tB);
        float aA = __expf(mA - mnA), aB = __expf(mB - mnB);
        mA = mnA; mB = mnB;
        float sumA = 0.f, sumB = 0.f;
#pragma unroll
        for (int nt = 0; nt < 8; nt++) {
            s[nt][0] = __expf(s[nt][0] - mnA);
            s[nt][1] = __expf(s[nt][1] - mnA);
            s[nt][2] = __expf(s[nt][2] - mnB);
            s[nt][3] = __expf(s[nt][3] - mnB);
            sumA += s[nt][0] + s[nt][1];
            sumB += s[nt][2] + s[nt][3];
        }
        sumA += __shfl_xor_sync(0xffffffffu, sumA, 1);
        sumA += __shfl_xor_sync(0xffffffffu, sumA, 2);
        sumB += __shfl_xor_sync(0xffffffffu, sumB, 1);
        sumB += __shfl_xor_sync(0xffffffffu, sumB, 2);
        lA = lA * aA + sumA;
        lB = lB * aB + sumB;
#pragma unroll
        for (int nt = 0; nt < 8; nt++) {
            o[nt][0] *= aA; o[nt][1] *= aA;
            o[nt][2] *= aB; o[nt][3] *= aB;
        }

        // ---- O += P V : P straight from registers (C layout == A-frag) ----
#pragma unroll
        for (int kk = 0; kk < 4; kk++) {
            unsigned pa0 = h2(s[2 * kk][0],     s[2 * kk][1]);
            unsigned pa1 = h2(s[2 * kk][2],     s[2 * kk][3]);
            unsigned pa2 = h2(s[2 * kk + 1][0], s[2 * kk + 1][1]);
            unsigned pa3 = h2(s[2 * kk + 1][2], s[2 * kk + 1][3]);
            uint4 v4[4];
#pragma unroll
            for (int ntp = 0; ntp < 4; ntp++)
                v4[ntp] = *(const uint4*)&bV[kk * 512 + ntp * 128 + lane * 4];
#pragma unroll
            for (int ntp = 0; ntp < 4; ntp++) {
#pragma unroll
                for (int e = 0; e < 2; e++) {
                    unsigned b0 = e ? v4[ntp].z : v4[ntp].x;
                    unsigned b1 = e ? v4[ntp].w : v4[ntp].y;
                    mma16(o[ntp * 2 + e], pa0, pa1, pa2, pa3, b0, b1);
                }
            }
        }
        __syncthreads();

        if (kt + 2 <= kthi) {
            ISSUE_KV(kt + 2, p);
        } else {
            asm volatile("cp.async.commit_group;");
        }
    }

    // ---- epilogue: normalize, write fp16 out-proj A-fragments ----
    float iA = 1.f / lA, iB = 1.f / lB;
    int q = b * Sc + qt * 64 + wid * 16 + (lane >> 2);
    int mblk = q >> 7, mtg = (q >> 4) & 7;
#pragma unroll
    for (int nt = 0; nt < 8; nt++) {
        int c0 = h * 64 + nt * 8 + 2 * (lane & 3);
        int kblk = c0 >> 5;
        int kstep = (c0 >> 4) & 1;
        int lanep = ((q & 7) << 2) | ((c0 >> 1) & 3);
        int slotb = ((c0 >> 3) & 1) << 1;
        size_t bidx = (size_t)(mblk * 32 + kblk) * 2048 + kstep * 1024
                    + mtg * 128 + lanep * 4 + slotb;
        Operm[bidx]     = h2(o[nt][0] * iA, o[nt][1] * iA);
        Operm[bidx + 1] = h2(o[nt][2] * iB, o[nt][3] * iB);
    }
#undef ISSUE_KV
}

// ---------------------------------------------------------------------------
extern "C" void kernel_launch(void* const* d_in, const int* in_sizes, int n_in,
                              void* d_out, int out_size)
{
    (void)in_sizes; (void)n_in; (void)out_size;
    const float* x     = (const float*)d_in[0];
    const float* in_w  = (const float*)d_in[1];
    const float* in_b  = (const float*)d_in[2];
    const float* out_w = (const float*)d_in[3];
    const float* out_b = (const float*)d_in[4];
    float* out = (float*)d_out;

    unsigned *xp, *ap, *wqp, *wop;
    cudaGetSymbolAddress((void**)&xp,  g_xperm);
    cudaGetSymbolAddress((void**)&ap,  g_attnperm);
    cudaGetSymbolAddress((void**)&wqp, g_wqkvperm);
    cudaGetSymbolAddress((void**)&wop, g_woutperm);

    const int M = Bc * Sc;                      // 4096
    const int smem_gemm = GSTAGES * 16384;      // 48 KB
    const int smem_attn = 12288 * 4;            // 48 KB -> 3 CTAs/SM
    cudaFuncSetAttribute(gemm_h,
                         cudaFuncAttributeMaxDynamicSharedMemorySize, smem_gemm);
    cudaFuncSetAttribute(gemm_qkv,
                         cudaFuncAttributeMaxDynamicSharedMemorySize, smem_gemm);
    cudaFuncSetAttribute(attn_mma,
                         cudaFuncAttributeMaxDynamicSharedMemorySize, smem_attn);

    // Operand packers (fp16)
    permA_h<<<(M * Dc / 2 + 255) / 256, 256>>>(x, xp, M, Dc);
    permB_h<<<(3 * Dc * Dc / 2 + 255) / 256, 256>>>(in_w, wqp, 3 * Dc, Dc);
    permB_h<<<(Dc * Dc / 2 + 255) / 256, 256>>>(out_w, wop, Dc, Dc);

    // 1) QKV projection with fused Q/K/V fragment-pack epilogue
    gemm_qkv<<<dim3(3 * Dc / 128, M / 128), 256, smem_gemm>>>(xp, wqp, in_b);

    // 2) fp16 tensor-core attention (writes out-proj A-fragments directly)
    attn_mma<<<dim3(Sc / 64, Hc, Bc), 128, smem_attn>>>(ap);

    // 3) Output projection
    gemm_h<<<dim3(Dc / 128, M / 128), 256, smem_gemm>>>(
        ap, wop, out_b, out, M, Dc, Dc);
}

// round 14
// speedup vs baseline: 7.3470x; 1.0532x over previous
#include <cuda_runtime.h>
#include <cuda_fp16.h>
#include <cstdint>

// Problem constants
#define Bc   2
#define Sc   2048
#define Dc   1024
#define Hc   16
#define HDc  64
#define Wc   128

// Scratch (allocation-free rule: __device__ globals). All fp16 fragments,
// stored as u32 words (2 halves each).
__device__ unsigned g_xperm[Bc * Sc * Dc / 2];     // x, A-frag layout
__device__ unsigned g_attnperm[Bc * Sc * Dc / 2];  // attn out, A-frag layout
__device__ unsigned g_wqkvperm[3 * Dc * Dc / 2];   // in_proj_w, B-frag layout
__device__ unsigned g_woutperm[Dc * Dc / 2];       // out_proj_w, B-frag layout
// Attention fragment buffers: per (b,h,tile64) block = 2048 words (8KB)
__device__ unsigned g_qfh[Bc * Hc * 32 * 2048];    // Q A-frag hi (scaled)
__device__ unsigned g_qfl[Bc * Hc * 32 * 2048];    // Q A-frag lo
__device__ unsigned g_kfh[Bc * Hc * 32 * 2048];    // K B-frag hi
__device__ unsigned g_kfl[Bc * Hc * 32 * 2048];    // K B-frag lo
__device__ unsigned g_vf [Bc * Hc * 32 * 2048];    // V^T B-frag (n=dim,k=key)

__device__ __forceinline__ unsigned h2(float a, float b) {
    __half2 t = __floats2half2_rn(a, b);
    return *reinterpret_cast<unsigned*>(&t);
}
__device__ __forceinline__ float hi16(float x) {
    return __half2float(__float2half_rn(x));
}

__device__ __forceinline__ void mma16(float* c, unsigned a0, unsigned a1,
                                      unsigned a2, unsigned a3,
                                      unsigned b0, unsigned b1) {
    asm volatile(
        "mma.sync.aligned.m16n8k16.row.col.f32.f16.f16.f32 "
        "{%0,%1,%2,%3}, {%4,%5,%6,%7}, {%8,%9}, {%0,%1,%2,%3};\n"
        : "+f"(c[0]), "+f"(c[1]), "+f"(c[2]), "+f"(c[3])
        : "r"(a0), "r"(a1), "r"(a2), "r"(a3), "r"(b0), "r"(b1));
}

// ---------------------------------------------------------------------------
// fp16 operand packers (unchanged, proven).
// ---------------------------------------------------------------------------
__global__ __launch_bounds__(256) void permA_h(
    const float* __restrict__ X, unsigned* __restrict__ P, int M, int K)
{
    int idx = blockIdx.x * 256 + threadIdx.x;
    if (idx >= (M * K) >> 1) return;
    int slot = idx & 3;
    int lane = (idx >> 2) & 31;
    int mtg  = (idx >> 7) & 7;
    int kstep = (idx >> 10) & 1;
    int rest = idx >> 11;
    int nKB = K >> 5;
    int kblk = rest % nKB, mblk = rest / nKB;
    int r = mblk * 128 + mtg * 16 + (slot & 1) * 8 + (lane >> 2);
    int d = kblk * 32 + kstep * 16 + ((slot >> 1) & 1) * 8 + 2 * (lane & 3);
    const float* x = X + (size_t)r * K + d;
    P[idx] = h2(x[0], x[1]);
}

__global__ __launch_bounds__(256) void permB_h(
    const float* __restrict__ X, unsigned* __restrict__ P, int N, int K)
{
    int idx = blockIdx.x * 256 + threadIdx.x;
    if (idx >= (N * K) >> 1) return;
    int slot = idx & 3;
    int lane = (idx >> 2) & 31;
    int ntp  = (idx >> 7) & 7;
    int kstep = (idx >> 10) & 1;
    int rest = idx >> 11;
    int nKB = K >> 5;
    int kblk = rest % nKB, nblk = rest / nKB;
    int e = (slot >> 1) & 1, kb = slot & 1;
    int n = nblk * 128 + ntp * 16 + e * 8 + (lane >> 2);
    int d = kblk * 32 + kstep * 16 + kb * 8 + 2 * (lane & 3);
    const float* x = X + (size_t)n * K + d;
    P[idx] = h2(x[0], x[1]);
}

// ---------------------------------------------------------------------------
// fp16 GEMM mainloop: 128x128 CTA tile, 4 warps (2x2), 64x64 warp tiles.
// K-tile 32, 3-stage cp.async (16KB/stage). 128B LDS per HMMA (was 192).
// ---------------------------------------------------------------------------
#define GSTAGES 3

#define ISSUE_TILE(t)                                                          \
    {                                                                          \
        uint32_t st = sbase + ((t) % GSTAGES) * 16384u;                        \
        const unsigned* asrc = Atile + (size_t)(t) * 2048;                     \
        const unsigned* bsrc = Btile + (size_t)(t) * 2048;                     \
        _Pragma("unroll")                                                      \
        for (int j = 0; j < 4; j++) {                                          \
            int c = tid + 128 * j;                                             \
            asm volatile("cp.async.cg.shared.global [%0],[%1],16;\n"           \
                         :: "r"(st + c * 16u), "l"(asrc + c * 4));             \
            asm volatile("cp.async.cg.shared.global [%0],[%1],16;\n"           \
                         :: "r"(st + 8192u + c * 16u), "l"(bsrc + c * 4));     \
        }                                                                      \
        asm volatile("cp.async.commit_group;\n");                              \
    }

#define GEMM_MAINLOOP(Ap_, Bp_, nKB_)                                          \
    float acc[4][8][4];                                                        \
    _Pragma("unroll")                                                          \
    for (int i = 0; i < 4; i++)                                                \
        _Pragma("unroll")                                                      \
        for (int j = 0; j < 8; j++)                                            \
            _Pragma("unroll")                                                  \
            for (int c = 0; c < 4; c++) acc[i][j][c] = 0.f;                    \
    const unsigned* Atile = (Ap_) + (size_t)blockIdx.y * (nKB_) * 2048;        \
    const unsigned* Btile = (Bp_) + (size_t)blockIdx.x * (nKB_) * 2048;        \
    const uint32_t sbase = (uint32_t)__cvta_generic_to_shared(smg);            \
    ISSUE_TILE(0);                                                             \
    ISSUE_TILE(1);                                                             \
    for (int t = 0; t < (nKB_); t++) {                                         \
        asm volatile("cp.async.wait_group 1;\n");                              \
        __syncthreads();                                                       \
        if (t + 2 < (nKB_)) { ISSUE_TILE(t + 2); }                             \
        else { asm volatile("cp.async.commit_group;\n"); }                     \
        const unsigned* sA = smg + (t % GSTAGES) * 4096;                       \
        const unsigned* sB = sA + 2048;                                        \
        _Pragma("unroll")                                                      \
        for (int ks = 0; ks < 2; ks++) {                                       \
            const int lx = lane << 2;                                          \
            uint4 af[4], bf[4];                                                \
            _Pragma("unroll")                                                  \
            for (int mt = 0; mt < 4; mt++)                                     \
                af[mt] = *(const uint4*)&sA[ks * 1024 + (warp_m * 4 + mt) * 128 + lx]; \
            _Pragma("unroll")                                                  \
            for (int p = 0; p < 4; p++)                                        \
                bf[p] = *(const uint4*)&sB[ks * 1024 + (warp_n * 4 + p) * 128 + lx]; \
            _Pragma("unroll")                                                  \
            for (int mt = 0; mt < 4; mt++) {                                   \
                _Pragma("unroll")                                              \
                for (int nt = 0; nt < 8; nt++) {                               \
                    const uint4& b4 = bf[nt >> 1];                             \
                    unsigned b0 = (nt & 1) ? b4.z : b4.x;                      \
                    unsigned b1 = (nt & 1) ? b4.w : b4.y;                      \
                    mma16(acc[mt][nt], af[mt].x, af[mt].y, af[mt].z, af[mt].w, b0, b1); \
                }                                                              \
            }                                                                  \
        }                                                                      \
    }

// ---------------------------------------------------------------------------
// Out-projection GEMM: row-major fp32 C + bias.
// ---------------------------------------------------------------------------
__global__ __launch_bounds__(128, 2) void gemm_h(
    const unsigned* __restrict__ Ap, const unsigned* __restrict__ Bp,
    const float* __restrict__ bias, float* __restrict__ C,
    int M, int N, int K)
{
    extern __shared__ unsigned smg[];
    const int tid    = threadIdx.x;
    const int lane   = tid & 31;
    const int wid    = tid >> 5;
    const int warp_m = wid >> 1;
    const int warp_n = wid & 1;
    const int nKB    = K >> 5;

    GEMM_MAINLOOP(Ap, Bp, nKB)

    const int m0 = blockIdx.y * 128;
    const int n0 = blockIdx.x * 128;
#pragma unroll
    for (int mt = 0; mt < 4; mt++) {
        int row = m0 + warp_m * 64 + mt * 16 + (lane >> 2);
#pragma unroll
        for (int nt = 0; nt < 8; nt++) {
            int col = n0 + warp_n * 64 + nt * 8 + 2 * (lane & 3);
            float2 bv = *(const float2*)&bias[col];
            float2 o0 = make_float2(acc[mt][nt][0] + bv.x, acc[mt][nt][1] + bv.y);
            float2 o1 = make_float2(acc[mt][nt][2] + bv.x, acc[mt][nt][3] + bv.y);
            *(float2*)&C[(size_t)row * N + col]       = o0;
            *(float2*)&C[(size_t)(row + 8) * N + col] = o1;
        }
    }
}

// ---------------------------------------------------------------------------
// QKV GEMM with fused fp16 fragment-pack epilogue.
// Grid.x: 0-7 Q, 8-15 K, 16-23 V (128-col bands).
// ---------------------------------------------------------------------------
__global__ __launch_bounds__(128, 2) void gemm_qkv(
    const unsigned* __restrict__ Ap, const unsigned* __restrict__ Bp,
    const float* __restrict__ bias)
{
    extern __shared__ unsigned smg[];
    const int tid    = threadIdx.x;
    const int lane   = tid & 31;
    const int wid    = tid >> 5;
    const int warp_m = wid >> 1;
    const int warp_n = wid & 1;
    const int nKB    = Dc >> 5;

    GEMM_MAINLOOP(Ap, Bp, nKB)

    const int m0 = blockIdx.y * 128;
    const int n0 = blockIdx.x * 128;
    const int kind = n0 >> 10;    // 0=Q, 1=K, 2=V
    __half* gv = (__half*)g_vf;

#pragma unroll
    for (int mt = 0; mt < 4; mt++) {
        int row = m0 + warp_m * 64 + mt * 16 + (lane >> 2);
#pragma unroll
        for (int nt = 0; nt < 8; nt++) {
            int col = n0 + warp_n * 64 + nt * 8 + 2 * (lane & 3);
            float2 bv = *(const float2*)&bias[col];
            float v0 = acc[mt][nt][0] + bv.x, v1 = acc[mt][nt][1] + bv.y;
            float v2 = acc[mt][nt][2] + bv.x, v3 = acc[mt][nt][3] + bv.y;

            int s = row & (Sc - 1), b = row >> 11;
            int cc = col & 1023;
            int h = cc >> 6, d = cc & 63;           // d even
            int sl = s & 63;
            size_t base = ((size_t)(b * Hc + h) * 32 + (s >> 6)) * 2048;

            if (kind == 0) {
                float q0 = v0 * 0.125f, q1 = v1 * 0.125f;
                float q2 = v2 * 0.125f, q3 = v3 * 0.125f;
                int idx = (d >> 4) * 512 + ((sl >> 4) & 3) * 128
                        + (((sl & 7) << 2) | ((d >> 1) & 3)) * 4
                        + (((d >> 3) & 1) << 1);
                g_qfh[base + idx]     = h2(q0, q1);
                g_qfh[base + idx + 1] = h2(q2, q3);
                g_qfl[base + idx]     = h2(q0 - hi16(q0), q1 - hi16(q1));
                g_qfl[base + idx + 1] = h2(q2 - hi16(q2), q3 - hi16(q3));
            } else if (kind == 1) {
                int idx = (d >> 4) * 512 + ((sl >> 4) & 3) * 128
                        + (((sl & 7) << 2) | ((d >> 1) & 3)) * 4
                        + ((d >> 3) & 1);
                g_kfh[base + idx]     = h2(v0, v1);       // e=0 (row s)
                g_kfh[base + idx + 2] = h2(v2, v3);       // e=1 (row s+8)
                g_kfl[base + idx]     = h2(v0 - hi16(v0), v1 - hi16(v1));
                g_kfl[base + idx + 2] = h2(v2 - hi16(v2), v3 - hi16(v3));
            } else {
                float vv[4] = {v0, v1, v2, v3};
#pragma unroll
                for (int e = 0; e < 4; e++) {
                    int key = sl + (e >> 1) * 8;
                    int dim = d + (e & 1);
                    int widx = (key >> 4) * 512 + ((dim >> 4) & 3) * 128
                             + (((dim & 7) << 2) | ((key >> 1) & 3)) * 4
                             + ((((dim >> 3) & 1) << 1) | ((key >> 3) & 1));
                    gv[(base + widx) * 2 + (key & 1)] = __float2half_rn(vv[e]);
                }
            }
        }
    }
}

// ---------------------------------------------------------------------------
// fp16 tensor-core windowed attention (unchanged from R13, proven).
// ---------------------------------------------------------------------------
__global__ __launch_bounds__(128, 3) void attn_mma(unsigned* __restrict__ Operm)
{
    extern __shared__ unsigned sm[];
    const int tid = threadIdx.x, lane = tid & 31, wid = tid >> 5;
    const int qt = blockIdx.x, h = blockIdx.y, b = blockIdx.z;
    const int bh = b * Hc + h;
    const uint32_t sbase = (uint32_t)__cvta_generic_to_shared(sm);

    {
        const unsigned* qh_ = g_qfh + ((size_t)bh * 32 + qt) * 2048;
        const unsigned* ql_ = g_qfl + ((size_t)bh * 32 + qt) * 2048;
#pragma unroll
        for (int j = 0; j < 4; j++) {
            int c = tid + 128 * j;
            asm volatile("cp.async.cg.shared.global [%0],[%1],16;"
                         :: "r"(sbase + c * 16u), "l"(qh_ + c * 4));
            asm volatile("cp.async.cg.shared.global [%0],[%1],16;"
                         :: "r"(sbase + 8192u + c * 16u), "l"(ql_ + c * 4));
        }
        asm volatile("cp.async.commit_group;");
        asm volatile("cp.async.wait_group 0;");
    }
    __syncthreads();
    uint4 qh[4], ql[4];
#pragma unroll
    for (int ks = 0; ks < 4; ks++) {
        qh[ks] = *(const uint4*)&sm[ks * 512 + wid * 128 + lane * 4];
        ql[ks] = *(const uint4*)&sm[2048 + ks * 512 + wid * 128 + lane * 4];
    }
    __syncthreads();

    const int ktlo = (qt - 2 > 0) ? qt - 2 : 0;
    const int kthi = (qt + 2 < 31) ? qt + 2 : 31;
    const int nT = kthi - ktlo + 1;

#define ISSUE_KV(kt, p)                                                         \
    {                                                                           \
        const unsigned* kh_ = g_kfh + ((size_t)bh * 32 + (kt)) * 2048;          \
        const unsigned* kl_ = g_kfl + ((size_t)bh * 32 + (kt)) * 2048;          \
        const unsigned* v_  = g_vf  + ((size_t)bh * 32 + (kt)) * 2048;          \
        uint32_t dst = sbase + (p) * 24576u;                                    \
        _Pragma("unroll")                                                       \
        for (int j = 0; j < 4; j++) {                                           \
            int c = tid + 128 * j;                                              \
            asm volatile("cp.async.cg.shared.global [%0],[%1],16;"              \
                         :: "r"(dst + c * 16u), "l"(kh_ + c * 4));              \
            asm volatile("cp.async.cg.shared.global [%0],[%1],16;"              \
                         :: "r"(dst + 8192u + c * 16u), "l"(kl_ + c * 4));      \
            asm volatile("cp.async.cg.shared.global [%0],[%1],16;"              \
                         :: "r"(dst + 16384u + c * 16u), "l"(v_ + c * 4));      \
        }                                                                       \
        asm volatile("cp.async.commit_group;");                                 \
    }

    ISSUE_KV(ktlo, 0);
    ISSUE_KV(ktlo + 1, 1);

    float o[8][4];
#pragma unroll
    for (int i = 0; i < 8; i++)
#pragma unroll
        for (int c = 0; c < 4; c++) o[i][c] = 0.f;
    float mA = -1e30f, mB = -1e30f, lA = 0.f, lB = 0.f;

    for (int j = 0; j < nT; j++) {
        const int kt = ktlo + j, p = j & 1;
        asm volatile("cp.async.wait_group 1;");
        __syncthreads();

        const unsigned* bKh = sm + p * 6144;
        const unsigned* bKl = bKh + 2048;
        const unsigned* bV  = bKh + 4096;

        float s[8][4];
#pragma unroll
        for (int i = 0; i < 8; i++)
#pragma unroll
            for (int c = 0; c < 4; c++) s[i][c] = 0.f;

#pragma unroll
        for (int ks = 0; ks < 4; ks++) {
            uint4 kh4[4], kl4[4];
#pragma unroll
            for (int ntp = 0; ntp < 4; ntp++) {
                kh4[ntp] = *(const uint4*)&bKh[ks * 512 + ntp * 128 + lane * 4];
                kl4[ntp] = *(const uint4*)&bKl[ks * 512 + ntp * 128 + lane * 4];
            }
#pragma unroll
            for (int ntp = 0; ntp < 4; ntp++) {
#pragma unroll
                for (int e = 0; e < 2; e++) {
                    unsigned bh0 = e ? kh4[ntp].z : kh4[ntp].x;
                    unsigned bh1 = e ? kh4[ntp].w : kh4[ntp].y;
                    unsigned bl0 = e ? kl4[ntp].z : kl4[ntp].x;
                    unsigned bl1 = e ? kl4[ntp].w : kl4[ntp].y;
                    float* c = s[ntp * 2 + e];
                    mma16(c, qh[ks].x, qh[ks].y, qh[ks].z, qh[ks].w, bh0, bh1);
                    mma16(c, ql[ks].x, ql[ks].y, ql[ks].z, ql[ks].w, bh0, bh1);
                    mma16(c, qh[ks].x, qh[ks].y, qh[ks].z, qh[ks].w, bl0, bl1);
                }
            }
        }

        if (kt - qt == 2 || qt - kt == 2) {
            int q1 = qt * 64 + wid * 16 + (lane >> 2);
            int k00 = kt * 64 + 2 * (lane & 3);
#pragma unroll
            for (int nt = 0; nt < 8; nt++) {
#pragma unroll
                for (int ci = 0; ci < 4; ci++) {
                    int qv = q1 + ((ci >= 2) ? 8 : 0);
                    int kv = k00 + nt * 8 + (ci & 1);
                    int d = qv - kv; d = (d < 0) ? -d : d;
                    if (d > Wc) s[nt][ci] = -1e30f;
                }
            }
        }

        float tA = -1e30f, tB = -1e30f;
#pragma unroll
        for (int nt = 0; nt < 8; nt++) {
            tA = fmaxf(tA, fmaxf(s[nt][0], s[nt][1]));
            tB = fmaxf(tB, fmaxf(s[nt][2], s[nt][3]));
        }
        tA = fmaxf(tA, __shfl_xor_sync(0xffffffffu, tA, 1));
        tA = fmaxf(tA, __shfl_xor_sync(0xffffffffu, tA, 2));
        tB = fmaxf(tB, __shfl_xor_sync(0xffffffffu, tB, 1));
        tB = fmaxf(tB, __shfl_xor_sync(0xffffffffu, tB, 2));
        float mnA = fmaxf(mA, tA), mnB = fmaxf(mB, tB);
        float aA = __expf(mA - mnA), aB = __expf(mB - mnB);
        mA = mnA; mB = mnB;
        float sumA = 0.f, sumB = 0.f;
#pragma unroll
        for (int nt = 0; nt < 8; nt++) {
            s[nt][0] = __expf(s[nt][0] - mnA);
            s[nt][1] = __expf(s[nt][1] - mnA);
            s[nt][2] = __expf(s[nt][2] - mnB);
            s[nt][3] = __expf(s[nt][3] - mnB);
            sumA += s[nt][0] + s[nt][1];
            sumB += s[nt][2] + s[nt][3];
        }
        sumA += __shfl_xor_sync(0xffffffffu, sumA, 1);
        sumA += __shfl_xor_sync(0xffffffffu, sumA, 2);
        sumB += __shfl_xor_sync(0xffffffffu, sumB, 1);
        sumB += __shfl_xor_sync(0xffffffffu, sumB, 2);
        lA = lA * aA + sumA;
        lB = lB * aB + sumB;
#pragma unroll
        for (int nt = 0; nt < 8; nt++) {
            o[nt][0] *= aA; o[nt][1] *= aA;
            o[nt][2] *= aB; o[nt][3] *= aB;
        }

#pragma unroll
        for (int kk = 0; kk < 4; kk++) {
            unsigned pa0 = h2(s[2 * kk][0],     s[2 * kk][1]);
            unsigned pa1 = h2(s[2 * kk][2],     s[2 * kk][3]);
            unsigned pa2 = h2(s[2 * kk + 1][0], s[2 * kk + 1][1]);
            unsigned pa3 = h2(s[2 * kk + 1][2], s[2 * kk + 1][3]);
            uint4 v4[4];
#pragma unroll
            for (int ntp = 0; ntp < 4; ntp++)
                v4[ntp] = *(const uint4*)&bV[kk * 512 + ntp * 128 + lane * 4];
#pragma unroll
            for (int ntp = 0; ntp < 4; ntp++) {
#pragma unroll
                for (int e = 0; e < 2; e++) {
                    unsigned b0 = e ? v4[ntp].z : v4[ntp].x;
                    unsigned b1 = e ? v4[ntp].w : v4[ntp].y;
                    mma16(o[ntp * 2 + e], pa0, pa1, pa2, pa3, b0, b1);
                }
            }
        }
        __syncthreads();

        if (kt + 2 <= kthi) {
            ISSUE_KV(kt + 2, p);
        } else {
            asm volatile("cp.async.commit_group;");
        }
    }

    float iA = 1.f / lA, iB = 1.f / lB;
    int q = b * Sc + qt * 64 + wid * 16 + (lane >> 2);
    int mblk = q >> 7, mtg = (q >> 4) & 7;
#pragma unroll
    for (int nt = 0; nt < 8; nt++) {
        int c0 = h * 64 + nt * 8 + 2 * (lane & 3);
        int kblk = c0 >> 5;
        int kstep = (c0 >> 4) & 1;
        int lanep = ((q & 7) << 2) | ((c0 >> 1) & 3);
        int slotb = ((c0 >> 3) & 1) << 1;
        size_t bidx = (size_t)(mblk * 32 + kblk) * 2048 + kstep * 1024
                    + mtg * 128 + lanep * 4 + slotb;
        Operm[bidx]     = h2(o[nt][0] * iA, o[nt][1] * iA);
        Operm[bidx + 1] = h2(o[nt][2] * iB, o[nt][3] * iB);
    }
#undef ISSUE_KV
}

// ---------------------------------------------------------------------------
extern "C" void kernel_launch(void* const* d_in, const int* in_sizes, int n_in,
                              void* d_out, int out_size)
{
    (void)in_sizes; (void)n_in; (void)out_size;
    const float* x     = (const float*)d_in[0];
    const float* in_w  = (const float*)d_in[1];
    const float* in_b  = (const float*)d_in[2];
    const float* out_w = (const float*)d_in[3];
    const float* out_b = (const float*)d_in[4];
    float* out = (float*)d_out;

    unsigned *xp, *ap, *wqp, *wop;
    cudaGetSymbolAddress((void**)&xp,  g_xperm);
    cudaGetSymbolAddress((void**)&ap,  g_attnperm);
    cudaGetSymbolAddress((void**)&wqp, g_wqkvperm);
    cudaGetSymbolAddress((void**)&wop, g_woutperm);

    const int M = Bc * Sc;                      // 4096
    const int smem_gemm = GSTAGES * 16384;      // 48 KB
    const int smem_attn = 12288 * 4;            // 48 KB -> 3 CTAs/SM
    cudaFuncSetAttribute(gemm_h,
                         cudaFuncAttributeMaxDynamicSharedMemorySize, smem_gemm);
    cudaFuncSetAttribute(gemm_qkv,
                         cudaFuncAttributeMaxDynamicSharedMemorySize, smem_gemm);
    cudaFuncSetAttribute(attn_mma,
                         cudaFuncAttributeMaxDynamicSharedMemorySize, smem_attn);

    // Operand packers (fp16)
    permA_h<<<(M * Dc / 2 + 255) / 256, 256>>>(x, xp, M, Dc);
    permB_h<<<(3 * Dc * Dc / 2 + 255) / 256, 256>>>(in_w, wqp, 3 * Dc, Dc);
    permB_h<<<(Dc * Dc / 2 + 255) / 256, 256>>>(out_w, wop, Dc, Dc);

    // 1) QKV projection with fused Q/K/V fragment-pack epilogue
    gemm_qkv<<<dim3(3 * Dc / 128, M / 128), 128, smem_gemm>>>(xp, wqp, in_b);

    // 2) fp16 tensor-core attention (writes out-proj A-fragments directly)
    attn_mma<<<dim3(Sc / 64, Hc, Bc), 128, smem_attn>>>(ap);

    // 3) Output projection
    gemm_h<<<dim3(Dc / 128, M / 128), 128, smem_gemm>>>(
        ap, wop, out_b, out, M, Dc, Dc);
}